// round 1
// baseline (speedup 1.0000x reference)
#include <cuda_runtime.h>
#include <math.h>

// Problem dims
#define B_   2
#define T_   512
#define C_   768
#define H_   12
#define K_   64
#define L_   6
#define DFF_ 2688
#define V_   50304
#define M_   (B_*T_)   // 1024 rows

// ---------------- scratch (device globals; no allocation allowed) ----------
__device__ float g_x    [M_*C_];
__device__ float g_ln   [M_*C_];
__device__ float g_a0   [M_*C_];
__device__ float g_a1   [M_*C_];
__device__ float g_a2   [M_*C_];
__device__ float g_a3   [M_*C_];
__device__ float g_r    [M_*C_];
__device__ float g_k    [M_*C_];
__device__ float g_v    [M_*C_];
__device__ float g_g    [M_*C_];
__device__ float g_wkv  [M_*C_];
__device__ float g_gated[M_*C_];
__device__ float g_hid  [M_*DFF_];
__device__ float g_gate [M_*C_];

// ---------------- LayerNorm over C=768 (one block / row, 256 threads) ------
__global__ void ln_kernel(const float* __restrict__ in,
                          const int*   __restrict__ tokens,   // null => direct rows
                          float*       __restrict__ out,
                          const float* __restrict__ s,
                          const float* __restrict__ bia,
                          float eps)
{
    int row = blockIdx.x;
    const float* xp = tokens ? (in + (size_t)tokens[row]*C_)
                             : (in + (size_t)row*C_);
    int tid = threadIdx.x;                 // 256
    float v0 = xp[tid], v1 = xp[tid+256], v2 = xp[tid+512];

    __shared__ float red[8];
    __shared__ float s_mean, s_rstd;

    float sum = v0 + v1 + v2;
    #pragma unroll
    for (int o=16;o;o>>=1) sum += __shfl_xor_sync(0xffffffffu, sum, o);
    if ((tid & 31) == 0) red[tid>>5] = sum;
    __syncthreads();
    if (tid == 0) { float t=0.f; for (int i=0;i<8;i++) t += red[i]; s_mean = t*(1.f/C_); }
    __syncthreads();
    float m  = s_mean;
    float d0 = v0-m, d1 = v1-m, d2 = v2-m;
    float sq = d0*d0 + d1*d1 + d2*d2;
    #pragma unroll
    for (int o=16;o;o>>=1) sq += __shfl_xor_sync(0xffffffffu, sq, o);
    __syncthreads();                       // protect red reuse
    if ((tid & 31) == 0) red[tid>>5] = sq;
    __syncthreads();
    if (tid == 0) { float t=0.f; for (int i=0;i<8;i++) t += red[i];
                    s_rstd = rsqrtf(t*(1.f/C_) + eps); }
    __syncthreads();
    float rs = s_rstd;
    float* op = out + (size_t)row*C_;
    op[tid]     = d0*rs*s[tid]     + bia[tid];
    op[tid+256] = d1*rs*s[tid+256] + bia[tid+256];
    op[tid+512] = d2*rs*s[tid+512] + bia[tid+512];
}

// ---------------- token-shift + 4-way lerp (time mixer) --------------------
__global__ void lerp4_kernel(const float* __restrict__ ln,
                             const float* __restrict__ tr, const float* __restrict__ tk,
                             const float* __restrict__ tv, const float* __restrict__ tg,
                             float* __restrict__ xr, float* __restrict__ xk,
                             float* __restrict__ xv, float* __restrict__ xg)
{
    int idx = blockIdx.x*blockDim.x + threadIdx.x;
    if (idx >= M_*C_) return;
    int c = idx % C_;
    int t = (idx / C_) % T_;
    float x  = ln[idx];
    float xs = (t == 0) ? 0.f : ln[idx - C_];
    float d  = xs - x;
    xr[idx] = fmaf(tr[c], d, x);
    xk[idx] = fmaf(tk[c], d, x);
    xv[idx] = fmaf(tv[c], d, x);
    xg[idx] = fmaf(tg[c], d, x);
}

// ---------------- token-shift + 2-way lerp (channel mixer) -----------------
__global__ void lerp2_kernel(const float* __restrict__ ln,
                             const float* __restrict__ ti, const float* __restrict__ tg,
                             float* __restrict__ xi, float* __restrict__ xg)
{
    int idx = blockIdx.x*blockDim.x + threadIdx.x;
    if (idx >= M_*C_) return;
    int c = idx % C_;
    int t = (idx / C_) % T_;
    float x  = ln[idx];
    float xs = (t == 0) ? 0.f : ln[idx - C_];
    float d  = xs - x;
    xi[idx] = fmaf(ti[c], d, x);
    xg[idx] = fmaf(tg[c], d, x);
}

// ---------------- SGEMM: C[M,N] = A[M,K] @ B[N,K]^T + epilogue -------------
// EPI: 0 none | 1 relu()^2 | 2 sigmoid | 3 +Res | 4 *Gate + Res
// BM=BN=64, BK=16, 256 threads, 4x4 per thread. All dims divisible.
template<int EPI>
__global__ void __launch_bounds__(256)
gemm_kernel(const float* __restrict__ A, const float* __restrict__ Bm,
            float* __restrict__ C,
            const float* __restrict__ Res, const float* __restrict__ Gate,
            int M, int N, int K)
{
    __shared__ __align__(16) float As[16][68];
    __shared__ __align__(16) float Bs[16][68];

    int bn = blockIdx.x * 64;
    int bm = blockIdx.y * 64;
    int tid = threadIdx.x;
    int tx = tid & 15, ty = tid >> 4;
    int lr = tid >> 2;            // 0..63 : row within tile
    int lk = (tid & 3) * 4;       // 0,4,8,12 : k offset

    const float* Aload = A  + (size_t)(bm + lr)*K + lk;
    const float* Bload = Bm + (size_t)(bn + lr)*K + lk;

    float acc[4][4] = {};

    for (int k0 = 0; k0 < K; k0 += 16) {
        float4 a4 = *(const float4*)(Aload + k0);
        float4 b4 = *(const float4*)(Bload + k0);
        __syncthreads();
        As[lk+0][lr]=a4.x; As[lk+1][lr]=a4.y; As[lk+2][lr]=a4.z; As[lk+3][lr]=a4.w;
        Bs[lk+0][lr]=b4.x; Bs[lk+1][lr]=b4.y; Bs[lk+2][lr]=b4.z; Bs[lk+3][lr]=b4.w;
        __syncthreads();
        #pragma unroll
        for (int kk = 0; kk < 16; kk++) {
            float4 av = *(const float4*)&As[kk][ty*4];
            float4 bv = *(const float4*)&Bs[kk][tx*4];
            float a[4] = {av.x, av.y, av.z, av.w};
            float b[4] = {bv.x, bv.y, bv.z, bv.w};
            #pragma unroll
            for (int i = 0; i < 4; i++)
                #pragma unroll
                for (int j = 0; j < 4; j++)
                    acc[i][j] = fmaf(a[i], b[j], acc[i][j]);
        }
    }

    #pragma unroll
    for (int i = 0; i < 4; i++) {
        int r = bm + ty*4 + i;
        #pragma unroll
        for (int j = 0; j < 4; j++) {
            int c = bn + tx*4 + j;
            size_t o = (size_t)r*N + c;
            float v = acc[i][j];
            if (EPI == 1) { v = fmaxf(v, 0.f); v = v*v; }
            if (EPI == 2) { v = 1.f/(1.f + expf(-v)); }
            if (EPI == 3) { v += Res[o]; }
            if (EPI == 4) { v = fmaf(v, Gate[o], Res[o]); }
            C[o] = v;
        }
    }
}

// ---------------- WKV sequential scan ---------------------------------------
// grid: B*H*2 blocks (v split in halves of 32), 128 threads.
// tid = vloc*4 + kc : 4 lanes split the k-sum (16 k's each), shuffle-reduce.
__global__ void wkv_kernel(const float* __restrict__ r, const float* __restrict__ k,
                           const float* __restrict__ v, float* __restrict__ out,
                           const float* __restrict__ bonus, const float* __restrict__ decay)
{
    int blk  = blockIdx.x;          // b*H*2 + h*2 + vs
    int vs   = blk & 1;
    int h    = (blk >> 1) % H_;
    int b    = blk / (2*H_);
    int tid  = threadIdx.x;         // 128
    int kc   = tid & 3;
    int vloc = tid >> 2;            // 0..31
    int vg   = vs*32 + vloc;

    size_t off = (size_t)b*T_*C_ + (size_t)h*K_;
    const float* rp = r + off;
    const float* kp = k + off;
    const float* vp = v + off;
    float*       op = out + off;

    float u[16], w[16], st[16];
    #pragma unroll
    for (int i = 0; i < 16; i++) {
        int kk = kc*16 + i;
        u[i]  = bonus[h*K_ + kk];
        w[i]  = expf(-expf(decay[h*K_ + kk]));
        st[i] = 0.f;
    }

    __shared__ float shr[64], shk[64];

    for (int t = 0; t < T_; t++) {
        __syncthreads();
        if (tid < 64) shr[tid]      = rp[(size_t)t*C_ + tid];
        else          shk[tid - 64] = kp[(size_t)t*C_ + (tid - 64)];
        __syncthreads();
        float vv  = vp[(size_t)t*C_ + vg];
        float acc = 0.f;
        #pragma unroll
        for (int i = 0; i < 16; i++) {
            float kkv = shk[kc*16 + i] * vv;
            acc   = fmaf(shr[kc*16 + i], fmaf(u[i], kkv, st[i]), acc);
            st[i] = fmaf(st[i], w[i], kkv);
        }
        acc += __shfl_xor_sync(0xffffffffu, acc, 1);
        acc += __shfl_xor_sync(0xffffffffu, acc, 2);
        if (kc == 0) op[(size_t)t*C_ + vg] = acc;
    }
}

// ---------------- GroupNorm(H groups of 64) * silu(g) ----------------------
// one warp per (b,t,h) group; 128 threads = 4 groups per block.
__global__ void gn_silu_kernel(const float* __restrict__ x, const float* __restrict__ g,
                               float* __restrict__ out,
                               const float* __restrict__ s, const float* __restrict__ bb)
{
    int gid  = blockIdx.x*4 + (threadIdx.x >> 5);  // over B*T*H
    int lane = threadIdx.x & 31;
    int h    = gid % H_;
    int row  = gid / H_;

    const float* xp = x + (size_t)row*C_ + h*K_;
    float x0 = xp[lane], x1 = xp[lane+32];
    float sum = x0 + x1;
    #pragma unroll
    for (int o=16;o;o>>=1) sum += __shfl_xor_sync(0xffffffffu, sum, o);
    float m  = sum * (1.f/64.f);
    float d0 = x0-m, d1 = x1-m;
    float sq = d0*d0 + d1*d1;
    #pragma unroll
    for (int o=16;o;o>>=1) sq += __shfl_xor_sync(0xffffffffu, sq, o);
    float rstd = rsqrtf(sq*(1.f/64.f) + 0.00064f);

    int c0 = h*K_ + lane, c1 = c0 + 32;
    float y0 = fmaf(d0*rstd, s[c0], bb[c0]);
    float y1 = fmaf(d1*rstd, s[c1], bb[c1]);

    const float* gp = g + (size_t)row*C_ + h*K_;
    float g0 = gp[lane], g1 = gp[lane+32];
    y0 *= g0 / (1.f + expf(-g0));
    y1 *= g1 / (1.f + expf(-g1));

    float* opp = out + (size_t)row*C_ + h*K_;
    opp[lane]    = y0;
    opp[lane+32] = y1;
}

// ---------------- orchestration --------------------------------------------
extern "C" void kernel_launch(void* const* d_in, const int* in_sizes, int n_in,
                              void* d_out, int out_size)
{
    (void)in_sizes; (void)n_in; (void)out_size;
    const int*   tokens    = (const int*)  d_in[0];
    const float* embed     = (const float*)d_in[1];
    const float* emb_ln_s  = (const float*)d_in[2];
    const float* emb_ln_b  = (const float*)d_in[3];
    const float* tm_ln_s   = (const float*)d_in[4];
    const float* tm_ln_b   = (const float*)d_in[5];
    const float* ts_r      = (const float*)d_in[6];
    const float* ts_k      = (const float*)d_in[7];
    const float* ts_v      = (const float*)d_in[8];
    const float* ts_g      = (const float*)d_in[9];
    const float* W_r       = (const float*)d_in[10];
    const float* W_k       = (const float*)d_in[11];
    const float* W_v       = (const float*)d_in[12];
    const float* W_g       = (const float*)d_in[13];
    const float* W_o       = (const float*)d_in[14];
    const float* bonus     = (const float*)d_in[15];
    const float* decay     = (const float*)d_in[16];
    const float* gn_s      = (const float*)d_in[17];
    const float* gn_b      = (const float*)d_in[18];
    const float* cm_ln_s   = (const float*)d_in[19];
    const float* cm_ln_b   = (const float*)d_in[20];
    const float* cm_ts_in  = (const float*)d_in[21];
    const float* cm_ts_g   = (const float*)d_in[22];
    const float* W_in      = (const float*)d_in[23];
    const float* W_out     = (const float*)d_in[24];
    const float* W_gate    = (const float*)d_in[25];
    const float* head_ln_s = (const float*)d_in[26];
    const float* head_ln_b = (const float*)d_in[27];
    const float* W_unembed = (const float*)d_in[28];

    float *x, *ln, *a0, *a1, *a2, *a3, *r, *k, *v, *g, *wkv, *gated, *hid, *gate;
    cudaGetSymbolAddress((void**)&x,     g_x);
    cudaGetSymbolAddress((void**)&ln,    g_ln);
    cudaGetSymbolAddress((void**)&a0,    g_a0);
    cudaGetSymbolAddress((void**)&a1,    g_a1);
    cudaGetSymbolAddress((void**)&a2,    g_a2);
    cudaGetSymbolAddress((void**)&a3,    g_a3);
    cudaGetSymbolAddress((void**)&r,     g_r);
    cudaGetSymbolAddress((void**)&k,     g_k);
    cudaGetSymbolAddress((void**)&v,     g_v);
    cudaGetSymbolAddress((void**)&g,     g_g);
    cudaGetSymbolAddress((void**)&wkv,   g_wkv);
    cudaGetSymbolAddress((void**)&gated, g_gated);
    cudaGetSymbolAddress((void**)&hid,   g_hid);
    cudaGetSymbolAddress((void**)&gate,  g_gate);

    const dim3 gC(C_/64,   M_/64);   // (12,16)
    const dim3 gF(DFF_/64, M_/64);   // (42,16)
    const dim3 gV(V_/64,   M_/64);   // (786,16)
    const int  EW_BLOCKS = (M_*C_ + 255)/256;

    // embedding gather + LN
    ln_kernel<<<M_, 256>>>(embed, tokens, x, emb_ln_s, emb_ln_b, 1e-5f);

    for (int l = 0; l < L_; l++) {
        const float* lnr  = ts_r   + l*C_;
        const float* lnk  = ts_k   + l*C_;
        const float* lnv  = ts_v   + l*C_;
        const float* lng  = ts_g   + l*C_;
        size_t cc  = (size_t)l*C_*C_;
        size_t fc  = (size_t)l*DFF_*C_;
        size_t hk  = (size_t)l*H_*K_;

        // ---- time mixer ----
        ln_kernel<<<M_, 256>>>(x, nullptr, ln, tm_ln_s + l*C_, tm_ln_b + l*C_, 1e-5f);
        lerp4_kernel<<<EW_BLOCKS, 256>>>(ln, lnr, lnk, lnv, lng, a0, a1, a2, a3);
        gemm_kernel<0><<<gC, 256>>>(a0, W_r + cc, r, nullptr, nullptr, M_, C_, C_);
        gemm_kernel<0><<<gC, 256>>>(a1, W_k + cc, k, nullptr, nullptr, M_, C_, C_);
        gemm_kernel<0><<<gC, 256>>>(a2, W_v + cc, v, nullptr, nullptr, M_, C_, C_);
        gemm_kernel<0><<<gC, 256>>>(a3, W_g + cc, g, nullptr, nullptr, M_, C_, C_);
        wkv_kernel<<<B_*H_*2, 128>>>(r, k, v, wkv, bonus + hk, decay + hk);
        gn_silu_kernel<<<(M_*H_)/4, 128>>>(wkv, g, gated, gn_s + l*C_, gn_b + l*C_);
        gemm_kernel<3><<<gC, 256>>>(gated, W_o + cc, x, x, nullptr, M_, C_, C_);

        // ---- channel mixer ----
        ln_kernel<<<M_, 256>>>(x, nullptr, ln, cm_ln_s + l*C_, cm_ln_b + l*C_, 1e-5f);
        lerp2_kernel<<<EW_BLOCKS, 256>>>(ln, cm_ts_in + l*C_, cm_ts_g + l*C_, a0, a1);
        gemm_kernel<1><<<gF, 256>>>(a0, W_in  + fc, hid,  nullptr, nullptr, M_, DFF_, C_);
        gemm_kernel<2><<<gC, 256>>>(a1, W_gate + cc, gate, nullptr, nullptr, M_, C_,   C_);
        gemm_kernel<4><<<(dim3(C_/64, M_/64)), 256>>>(hid, W_out + (size_t)l*C_*DFF_, x,
                                                      x, gate, M_, C_, DFF_);
    }

    // head LN + unembed
    ln_kernel<<<M_, 256>>>(x, nullptr, ln, head_ln_s, head_ln_b, 1e-5f);
    gemm_kernel<0><<<gV, 256>>>(ln, W_unembed, (float*)d_out, nullptr, nullptr,
                                M_, V_, C_);
}

// round 2
// speedup vs baseline: 1.2272x; 1.2272x over previous
#include <cuda_runtime.h>
#include <math.h>
#include <mma.h>

using namespace nvcuda;

// Problem dims
#define B_   2
#define T_   512
#define C_   768
#define H_   12
#define K_   64
#define L_   6
#define DFF_ 2688
#define V_   50304
#define M_   (B_*T_)   // 1024 rows

// ---------------- scratch (device globals; no allocation allowed) ----------
__device__ float g_x    [M_*C_];
__device__ float g_ln   [M_*C_];
__device__ float g_a    [4*M_*C_];   // lerp outputs (batched)
__device__ float g_rkvg [4*M_*C_];   // r,k,v,g (batched)
__device__ float g_wkv  [M_*C_];
__device__ float g_gated[M_*C_];
__device__ float g_hid  [M_*DFF_];
__device__ float g_gate [M_*C_];

// ---------------- LayerNorm over C=768 (one block / row, 256 threads) ------
__global__ void ln_kernel(const float* __restrict__ in,
                          const int*   __restrict__ tokens,   // null => direct rows
                          float*       __restrict__ out,
                          const float* __restrict__ s,
                          const float* __restrict__ bia,
                          float eps)
{
    int row = blockIdx.x;
    const float* xp = tokens ? (in + (size_t)tokens[row]*C_)
                             : (in + (size_t)row*C_);
    int tid = threadIdx.x;                 // 256
    float v0 = xp[tid], v1 = xp[tid+256], v2 = xp[tid+512];

    __shared__ float red[8];
    __shared__ float s_mean, s_rstd;

    float sum = v0 + v1 + v2;
    #pragma unroll
    for (int o=16;o;o>>=1) sum += __shfl_xor_sync(0xffffffffu, sum, o);
    if ((tid & 31) == 0) red[tid>>5] = sum;
    __syncthreads();
    if (tid == 0) { float t=0.f; for (int i=0;i<8;i++) t += red[i]; s_mean = t*(1.f/C_); }
    __syncthreads();
    float m  = s_mean;
    float d0 = v0-m, d1 = v1-m, d2 = v2-m;
    float sq = d0*d0 + d1*d1 + d2*d2;
    #pragma unroll
    for (int o=16;o;o>>=1) sq += __shfl_xor_sync(0xffffffffu, sq, o);
    __syncthreads();
    if ((tid & 31) == 0) red[tid>>5] = sq;
    __syncthreads();
    if (tid == 0) { float t=0.f; for (int i=0;i<8;i++) t += red[i];
                    s_rstd = rsqrtf(t*(1.f/C_) + eps); }
    __syncthreads();
    float rs = s_rstd;
    float* op = out + (size_t)row*C_;
    op[tid]     = d0*rs*s[tid]     + bia[tid];
    op[tid+256] = d1*rs*s[tid+256] + bia[tid+256];
    op[tid+512] = d2*rs*s[tid+512] + bia[tid+512];
}

// ---------------- token-shift + 4-way lerp (time mixer) --------------------
__global__ void lerp4_kernel(const float* __restrict__ ln,
                             const float* __restrict__ tr, const float* __restrict__ tk,
                             const float* __restrict__ tv, const float* __restrict__ tg,
                             float* __restrict__ aout)
{
    int idx = blockIdx.x*blockDim.x + threadIdx.x;
    if (idx >= M_*C_) return;
    int c = idx % C_;
    int t = (idx / C_) % T_;
    float x  = ln[idx];
    float xs = (t == 0) ? 0.f : ln[idx - C_];
    float d  = xs - x;
    aout[idx]            = fmaf(tr[c], d, x);
    aout[idx +   M_*C_]  = fmaf(tk[c], d, x);
    aout[idx + 2*M_*C_]  = fmaf(tv[c], d, x);
    aout[idx + 3*M_*C_]  = fmaf(tg[c], d, x);
}

// ---------------- token-shift + 2-way lerp (channel mixer) -----------------
__global__ void lerp2_kernel(const float* __restrict__ ln,
                             const float* __restrict__ ti, const float* __restrict__ tg,
                             float* __restrict__ xi, float* __restrict__ xg)
{
    int idx = blockIdx.x*blockDim.x + threadIdx.x;
    if (idx >= M_*C_) return;
    int c = idx % C_;
    int t = (idx / C_) % T_;
    float x  = ln[idx];
    float xs = (t == 0) ? 0.f : ln[idx - C_];
    float d  = xs - x;
    xi[idx] = fmaf(ti[c], d, x);
    xg[idx] = fmaf(tg[c], d, x);
}

// ---------------- TF32 tensor-core GEMM: C[M,N] = A[M,K] @ W[N,K]^T --------
// EPI: 0 none | 1 relu()^2 | 2 sigmoid | 3 +Res | 4 *Gate + Res
// 256 threads = 8 warps in a 2x4 grid; warp tile (BM/2) x (BN/4).
// grid.z = batch (A/C strided by M*K / M*N, W selected from W0..W3).
template<int BM, int BN, int EPI>
__global__ void __launch_bounds__(256)
tgemm(const float* __restrict__ Abase,
      const float* __restrict__ W0, const float* __restrict__ W1,
      const float* __restrict__ W2, const float* __restrict__ W3,
      float* __restrict__ Cbase,
      const float* __restrict__ Res, const float* __restrict__ Gate,
      int M, int N, int K)
{
    constexpr int LDT = 36;                 // 32 + pad, multiple of 4
    __shared__ __align__(16)  float As[BM*LDT];
    __shared__ __align__(16)  float Bs[BN*LDT];
    __shared__ __align__(128) float Ep[8*256];   // 16x16 per warp (EPI 3/4)

    int z = blockIdx.z;
    const float* A = Abase + (size_t)z*M*K;
    const float* W = W0;
    if (z == 1) W = W1; else if (z == 2) W = W2; else if (z == 3) W = W3;
    float* C = Cbase + (size_t)z*M*N;

    int bm = blockIdx.y*BM, bn = blockIdx.x*BN;
    int tid = threadIdx.x, warp = tid>>5, lane = tid&31;
    int wm = warp >> 2;           // 0..1
    int wn = warp & 3;            // 0..3
    constexpr int WM = BM/2;
    constexpr int WN = BN/4;
    constexpr int MF = WM/16, NF = WN/16;

    wmma::fragment<wmma::accumulator,16,16,8,float> cf[MF][NF];
    #pragma unroll
    for (int i=0;i<MF;i++)
        #pragma unroll
        for (int j=0;j<NF;j++) wmma::fill_fragment(cf[i][j], 0.f);

    constexpr int A_F4 = BM*8/256;   // float4 per thread for A tile
    constexpr int B_F4 = BN*8/256;

    for (int k0 = 0; k0 < K; k0 += 32) {
        __syncthreads();
        #pragma unroll
        for (int i=0;i<A_F4;i++){
            int idx = tid + i*256;           // over BM*8 float4
            int row = idx>>3, c4 = idx&7;
            float4 v = *(const float4*)(A + (size_t)(bm+row)*K + k0 + c4*4);
            *(float4*)&As[row*LDT + c4*4] = v;
        }
        #pragma unroll
        for (int i=0;i<B_F4;i++){
            int idx = tid + i*256;
            int row = idx>>3, c4 = idx&7;
            float4 v = *(const float4*)(W + (size_t)(bn+row)*K + k0 + c4*4);
            *(float4*)&Bs[row*LDT + c4*4] = v;
        }
        __syncthreads();
        #pragma unroll
        for (int kk=0; kk<32; kk+=8) {
            wmma::fragment<wmma::matrix_a,16,16,8,wmma::precision::tf32,wmma::row_major> af[MF];
            wmma::fragment<wmma::matrix_b,16,16,8,wmma::precision::tf32,wmma::col_major> bf[NF];
            #pragma unroll
            for (int i=0;i<MF;i++){
                wmma::load_matrix_sync(af[i], &As[(wm*WM + i*16)*LDT + kk], LDT);
                #pragma unroll
                for (int e=0;e<af[i].num_elements;e++)
                    af[i].x[e] = wmma::__float_to_tf32(af[i].x[e]);
            }
            #pragma unroll
            for (int j=0;j<NF;j++){
                wmma::load_matrix_sync(bf[j], &Bs[(wn*WN + j*16)*LDT + kk], LDT);
                #pragma unroll
                for (int e=0;e<bf[j].num_elements;e++)
                    bf[j].x[e] = wmma::__float_to_tf32(bf[j].x[e]);
            }
            #pragma unroll
            for (int i=0;i<MF;i++)
                #pragma unroll
                for (int j=0;j<NF;j++)
                    wmma::mma_sync(cf[i][j], af[i], bf[j], cf[i][j]);
        }
    }

    // ---- epilogue ----
    #pragma unroll
    for (int i=0;i<MF;i++){
        #pragma unroll
        for (int j=0;j<NF;j++){
            int r0 = bm + wm*WM + i*16;
            int c0 = bn + wn*WN + j*16;
            if (EPI == 0) {
                wmma::store_matrix_sync(&C[(size_t)r0*N + c0], cf[i][j], N, wmma::mem_row_major);
            } else if (EPI == 1 || EPI == 2) {
                #pragma unroll
                for (int e=0;e<cf[i][j].num_elements;e++){
                    float v = cf[i][j].x[e];
                    if (EPI == 1) { v = fmaxf(v, 0.f); v = v*v; }
                    else          { v = 1.f/(1.f + expf(-v)); }
                    cf[i][j].x[e] = v;
                }
                wmma::store_matrix_sync(&C[(size_t)r0*N + c0], cf[i][j], N, wmma::mem_row_major);
            } else {
                float* buf = &Ep[warp*256];
                wmma::store_matrix_sync(buf, cf[i][j], 16, wmma::mem_row_major);
                __syncwarp();
                #pragma unroll
                for (int e=0;e<8;e++){
                    int idx2 = lane*8 + e;      // 0..255
                    int rr = idx2>>4, cc2 = idx2&15;
                    size_t o = (size_t)(r0+rr)*N + (c0+cc2);
                    float v = buf[idx2];
                    if (EPI == 3) v += Res[o];
                    else          v = fmaf(v, Gate[o], Res[o]);
                    C[o] = v;
                }
                __syncwarp();
            }
        }
    }
}

// ---------------- WKV sequential scan ---------------------------------------
__global__ void wkv_kernel(const float* __restrict__ r, const float* __restrict__ k,
                           const float* __restrict__ v, float* __restrict__ out,
                           const float* __restrict__ bonus, const float* __restrict__ decay)
{
    int blk  = blockIdx.x;          // b*H*2 + h*2 + vs
    int vs   = blk & 1;
    int h    = (blk >> 1) % H_;
    int b    = blk / (2*H_);
    int tid  = threadIdx.x;         // 128
    int kc   = tid & 3;
    int vloc = tid >> 2;            // 0..31
    int vg   = vs*32 + vloc;

    size_t off = (size_t)b*T_*C_ + (size_t)h*K_;
    const float* rp = r + off;
    const float* kp = k + off;
    const float* vp = v + off;
    float*       op = out + off;

    float u[16], w[16], st[16];
    #pragma unroll
    for (int i = 0; i < 16; i++) {
        int kk = kc*16 + i;
        u[i]  = bonus[h*K_ + kk];
        w[i]  = expf(-expf(decay[h*K_ + kk]));
        st[i] = 0.f;
    }

    __shared__ float shr[64], shk[64];

    for (int t = 0; t < T_; t++) {
        __syncthreads();
        if (tid < 64) shr[tid]      = rp[(size_t)t*C_ + tid];
        else          shk[tid - 64] = kp[(size_t)t*C_ + (tid - 64)];
        __syncthreads();
        float vv  = vp[(size_t)t*C_ + vg];
        float acc = 0.f;
        #pragma unroll
        for (int i = 0; i < 16; i++) {
            float kkv = shk[kc*16 + i] * vv;
            acc   = fmaf(shr[kc*16 + i], fmaf(u[i], kkv, st[i]), acc);
            st[i] = fmaf(st[i], w[i], kkv);
        }
        acc += __shfl_xor_sync(0xffffffffu, acc, 1);
        acc += __shfl_xor_sync(0xffffffffu, acc, 2);
        if (kc == 0) op[(size_t)t*C_ + vg] = acc;
    }
}

// ---------------- GroupNorm(H groups of 64) * silu(g) ----------------------
__global__ void gn_silu_kernel(const float* __restrict__ x, const float* __restrict__ g,
                               float* __restrict__ out,
                               const float* __restrict__ s, const float* __restrict__ bb)
{
    int gid  = blockIdx.x*4 + (threadIdx.x >> 5);  // over B*T*H
    int lane = threadIdx.x & 31;
    int h    = gid % H_;
    int row  = gid / H_;

    const float* xp = x + (size_t)row*C_ + h*K_;
    float x0 = xp[lane], x1 = xp[lane+32];
    float sum = x0 + x1;
    #pragma unroll
    for (int o=16;o;o>>=1) sum += __shfl_xor_sync(0xffffffffu, sum, o);
    float m  = sum * (1.f/64.f);
    float d0 = x0-m, d1 = x1-m;
    float sq = d0*d0 + d1*d1;
    #pragma unroll
    for (int o=16;o;o>>=1) sq += __shfl_xor_sync(0xffffffffu, sq, o);
    float rstd = rsqrtf(sq*(1.f/64.f) + 0.00064f);

    int c0 = h*K_ + lane, c1 = c0 + 32;
    float y0 = fmaf(d0*rstd, s[c0], bb[c0]);
    float y1 = fmaf(d1*rstd, s[c1], bb[c1]);

    const float* gp = g + (size_t)row*C_ + h*K_;
    float g0 = gp[lane], g1 = gp[lane+32];
    y0 *= g0 / (1.f + expf(-g0));
    y1 *= g1 / (1.f + expf(-g1));

    float* opp = out + (size_t)row*C_ + h*K_;
    opp[lane]    = y0;
    opp[lane+32] = y1;
}

// ---------------- orchestration --------------------------------------------
extern "C" void kernel_launch(void* const* d_in, const int* in_sizes, int n_in,
                              void* d_out, int out_size)
{
    (void)in_sizes; (void)n_in; (void)out_size;
    const int*   tokens    = (const int*)  d_in[0];
    const float* embed     = (const float*)d_in[1];
    const float* emb_ln_s  = (const float*)d_in[2];
    const float* emb_ln_b  = (const float*)d_in[3];
    const float* tm_ln_s   = (const float*)d_in[4];
    const float* tm_ln_b   = (const float*)d_in[5];
    const float* ts_r      = (const float*)d_in[6];
    const float* ts_k      = (const float*)d_in[7];
    const float* ts_v      = (const float*)d_in[8];
    const float* ts_g      = (const float*)d_in[9];
    const float* W_r       = (const float*)d_in[10];
    const float* W_k       = (const float*)d_in[11];
    const float* W_v       = (const float*)d_in[12];
    const float* W_g       = (const float*)d_in[13];
    const float* W_o       = (const float*)d_in[14];
    const float* bonus     = (const float*)d_in[15];
    const float* decay     = (const float*)d_in[16];
    const float* gn_s      = (const float*)d_in[17];
    const float* gn_b      = (const float*)d_in[18];
    const float* cm_ln_s   = (const float*)d_in[19];
    const float* cm_ln_b   = (const float*)d_in[20];
    const float* cm_ts_in  = (const float*)d_in[21];
    const float* cm_ts_g   = (const float*)d_in[22];
    const float* W_in      = (const float*)d_in[23];
    const float* W_out     = (const float*)d_in[24];
    const float* W_gate    = (const float*)d_in[25];
    const float* head_ln_s = (const float*)d_in[26];
    const float* head_ln_b = (const float*)d_in[27];
    const float* W_unembed = (const float*)d_in[28];

    float *x, *ln, *a, *rkvg, *wkv, *gated, *hid, *gate;
    cudaGetSymbolAddress((void**)&x,     g_x);
    cudaGetSymbolAddress((void**)&ln,    g_ln);
    cudaGetSymbolAddress((void**)&a,     g_a);
    cudaGetSymbolAddress((void**)&rkvg,  g_rkvg);
    cudaGetSymbolAddress((void**)&wkv,   g_wkv);
    cudaGetSymbolAddress((void**)&gated, g_gated);
    cudaGetSymbolAddress((void**)&hid,   g_hid);
    cudaGetSymbolAddress((void**)&gate,  g_gate);

    const int EW_BLOCKS = (M_*C_ + 255)/256;

    // embedding gather + LN
    ln_kernel<<<M_, 256>>>(embed, tokens, x, emb_ln_s, emb_ln_b, 1e-5f);

    for (int l = 0; l < L_; l++) {
        size_t cc = (size_t)l*C_*C_;
        size_t fc = (size_t)l*DFF_*C_;
        size_t oc = (size_t)l*C_*DFF_;
        size_t hk = (size_t)l*H_*K_;

        // ---- time mixer ----
        ln_kernel<<<M_, 256>>>(x, nullptr, ln, tm_ln_s + l*C_, tm_ln_b + l*C_, 1e-5f);
        lerp4_kernel<<<EW_BLOCKS, 256>>>(ln, ts_r + l*C_, ts_k + l*C_,
                                         ts_v + l*C_, ts_g + l*C_, a);
        // r,k,v,g batched in one launch (grid.z = 4)
        tgemm<128,128,0><<<dim3(C_/128, M_/128, 4), 256>>>(
            a, W_r + cc, W_k + cc, W_v + cc, W_g + cc, rkvg,
            nullptr, nullptr, M_, C_, C_);
        wkv_kernel<<<B_*H_*2, 128>>>(rkvg, rkvg + M_*C_, rkvg + 2*M_*C_, wkv,
                                     bonus + hk, decay + hk);
        gn_silu_kernel<<<(M_*H_)/4, 128>>>(wkv, rkvg + 3*M_*C_, gated,
                                           gn_s + l*C_, gn_b + l*C_);
        tgemm<64,64,3><<<dim3(C_/64, M_/64, 1), 256>>>(
            gated, W_o + cc, nullptr, nullptr, nullptr, x,
            x, nullptr, M_, C_, C_);

        // ---- channel mixer ----
        ln_kernel<<<M_, 256>>>(x, nullptr, ln, cm_ln_s + l*C_, cm_ln_b + l*C_, 1e-5f);
        lerp2_kernel<<<EW_BLOCKS, 256>>>(ln, cm_ts_in + l*C_, cm_ts_g + l*C_,
                                         a, a + M_*C_);
        tgemm<128,128,1><<<dim3(DFF_/128, M_/128, 1), 256>>>(
            a, W_in + fc, nullptr, nullptr, nullptr, hid,
            nullptr, nullptr, M_, DFF_, C_);
        tgemm<64,64,2><<<dim3(C_/64, M_/64, 1), 256>>>(
            a + M_*C_, W_gate + cc, nullptr, nullptr, nullptr, gate,
            nullptr, nullptr, M_, C_, C_);
        tgemm<64,64,4><<<dim3(C_/64, M_/64, 1), 256>>>(
            hid, W_out + oc, nullptr, nullptr, nullptr, x,
            x, gate, M_, C_, DFF_);
    }

    // head LN + unembed
    ln_kernel<<<M_, 256>>>(x, nullptr, ln, head_ln_s, head_ln_b, 1e-5f);
    tgemm<128,128,0><<<dim3(V_/128, M_/128, 1), 256>>>(
        ln, W_unembed, nullptr, nullptr, nullptr, (float*)d_out,
        nullptr, nullptr, M_, V_, C_);
}

// round 3
// speedup vs baseline: 1.2820x; 1.0447x over previous
#include <cuda_runtime.h>
#include <math.h>
#include <mma.h>

using namespace nvcuda;

// Problem dims
#define B_   2
#define T_   512
#define C_   768
#define H_   12
#define K_   64
#define L_   6
#define DFF_ 2688
#define V_   50304
#define M_   (B_*T_)   // 1024 rows

// ---------------- scratch (device globals; no allocation allowed) ----------
__device__ float g_x    [M_*C_];
__device__ float g_ln   [M_*C_];
__device__ float g_a    [4*M_*C_];   // lerp outputs (batched)
__device__ float g_rkvg [4*M_*C_];   // r,k,v,g (batched)
__device__ float g_wkv  [M_*C_];
__device__ float g_gated[M_*C_];
__device__ float g_hid  [M_*DFF_];
__device__ float g_gate [M_*C_];

// ---------------- cp.async helpers -----------------------------------------
__device__ __forceinline__ void cp_async16(void* smem_dst, const void* gsrc) {
    unsigned dst = (unsigned)__cvta_generic_to_shared(smem_dst);
    asm volatile("cp.async.cg.shared.global [%0], [%1], 16;\n" :: "r"(dst), "l"(gsrc));
}
__device__ __forceinline__ void cp_commit() {
    asm volatile("cp.async.commit_group;\n");
}
__device__ __forceinline__ void cp_wait1() {
    asm volatile("cp.async.wait_group 1;\n");
}
__device__ __forceinline__ void cp_wait0() {
    asm volatile("cp.async.wait_group 0;\n");
}

// ---------------- LayerNorm over C=768 (one block / row, 256 threads) ------
__global__ void ln_kernel(const float* __restrict__ in,
                          const int*   __restrict__ tokens,   // null => direct rows
                          float*       __restrict__ out,
                          const float* __restrict__ s,
                          const float* __restrict__ bia,
                          float eps)
{
    int row = blockIdx.x;
    const float* xp = tokens ? (in + (size_t)tokens[row]*C_)
                             : (in + (size_t)row*C_);
    int tid = threadIdx.x;                 // 256
    float v0 = xp[tid], v1 = xp[tid+256], v2 = xp[tid+512];

    __shared__ float red[8];
    __shared__ float s_mean, s_rstd;

    float sum = v0 + v1 + v2;
    #pragma unroll
    for (int o=16;o;o>>=1) sum += __shfl_xor_sync(0xffffffffu, sum, o);
    if ((tid & 31) == 0) red[tid>>5] = sum;
    __syncthreads();
    if (tid == 0) { float t=0.f; for (int i=0;i<8;i++) t += red[i]; s_mean = t*(1.f/C_); }
    __syncthreads();
    float m  = s_mean;
    float d0 = v0-m, d1 = v1-m, d2 = v2-m;
    float sq = d0*d0 + d1*d1 + d2*d2;
    #pragma unroll
    for (int o=16;o;o>>=1) sq += __shfl_xor_sync(0xffffffffu, sq, o);
    __syncthreads();
    if ((tid & 31) == 0) red[tid>>5] = sq;
    __syncthreads();
    if (tid == 0) { float t=0.f; for (int i=0;i<8;i++) t += red[i];
                    s_rstd = rsqrtf(t*(1.f/C_) + eps); }
    __syncthreads();
    float rs = s_rstd;
    float* op = out + (size_t)row*C_;
    op[tid]     = d0*rs*s[tid]     + bia[tid];
    op[tid+256] = d1*rs*s[tid+256] + bia[tid+256];
    op[tid+512] = d2*rs*s[tid+512] + bia[tid+512];
}

// ---------------- token-shift + 4-way lerp (time mixer) --------------------
__global__ void lerp4_kernel(const float* __restrict__ ln,
                             const float* __restrict__ tr, const float* __restrict__ tk,
                             const float* __restrict__ tv, const float* __restrict__ tg,
                             float* __restrict__ aout)
{
    int idx = blockIdx.x*blockDim.x + threadIdx.x;
    if (idx >= M_*C_) return;
    int c = idx % C_;
    int t = (idx / C_) % T_;
    float x  = ln[idx];
    float xs = (t == 0) ? 0.f : ln[idx - C_];
    float d  = xs - x;
    aout[idx]            = fmaf(tr[c], d, x);
    aout[idx +   M_*C_]  = fmaf(tk[c], d, x);
    aout[idx + 2*M_*C_]  = fmaf(tv[c], d, x);
    aout[idx + 3*M_*C_]  = fmaf(tg[c], d, x);
}

// ---------------- token-shift + 2-way lerp (channel mixer) -----------------
__global__ void lerp2_kernel(const float* __restrict__ ln,
                             const float* __restrict__ ti, const float* __restrict__ tg,
                             float* __restrict__ xi, float* __restrict__ xg)
{
    int idx = blockIdx.x*blockDim.x + threadIdx.x;
    if (idx >= M_*C_) return;
    int c = idx % C_;
    int t = (idx / C_) % T_;
    float x  = ln[idx];
    float xs = (t == 0) ? 0.f : ln[idx - C_];
    float d  = xs - x;
    xi[idx] = fmaf(ti[c], d, x);
    xg[idx] = fmaf(tg[c], d, x);
}

// ---------------- TF32 tensor-core GEMM, cp.async double-buffered ----------
// C[M,N] = A[M,K] @ W[N,K]^T + epilogue
// EPI: 0 none | 1 relu()^2 | 2 sigmoid | 3 +Res | 4 *Gate + Res
// 256 threads = 8 warps; warp tile (BM/2) x (BN/4). BK=16, 2 smem stages.
// grid.z = batch (A/C strided by M*K / M*N, W selected from W0..W3).
template<int BM, int BN, int EPI>
__global__ void __launch_bounds__(256)
tgemm(const float* __restrict__ Abase,
      const float* __restrict__ W0, const float* __restrict__ W1,
      const float* __restrict__ W2, const float* __restrict__ W3,
      float* __restrict__ Cbase,
      const float* __restrict__ Res, const float* __restrict__ Gate,
      int M, int N, int K)
{
    constexpr int BK  = 16;
    constexpr int LDT = 20;                 // 16 + pad (80B rows, 16B aligned)
    __shared__ __align__(16) float As[2][BM*LDT];
    __shared__ __align__(16) float Bs[2][BN*LDT];
    __shared__ __align__(16) float Ep[(EPI >= 3) ? 8*256 : 8];

    int z = blockIdx.z;
    const float* A = Abase + (size_t)z*M*K;
    const float* W = W0;
    if (z == 1) W = W1; else if (z == 2) W = W2; else if (z == 3) W = W3;
    float* C = Cbase + (size_t)z*M*N;

    int bm = blockIdx.y*BM, bn = blockIdx.x*BN;
    int tid = threadIdx.x, warp = tid>>5, lane = tid&31;
    int wm = warp >> 2;           // 0..1
    int wn = warp & 3;            // 0..3
    constexpr int WM = BM/2;
    constexpr int WN = BN/4;
    constexpr int MF = WM/16, NF = WN/16;

    wmma::fragment<wmma::accumulator,16,16,8,float> cf[MF][NF];
    #pragma unroll
    for (int i=0;i<MF;i++)
        #pragma unroll
        for (int j=0;j<NF;j++) wmma::fill_fragment(cf[i][j], 0.f);

    // per-stage copy footprint: BM*BK/4 float4 for A, BN*BK/4 for B
    constexpr int A_F4 = BM*(BK/4)/256;   // 2 for BM=128, 1 for BM=64
    constexpr int B_F4 = BN*(BK/4)/256;

    const int nK = K / BK;

    auto issue_stage = [&](int stg, int kt) {
        int k0 = kt*BK;
        #pragma unroll
        for (int i=0;i<A_F4;i++){
            int idx = tid + i*256;               // over BM*4 float4
            int row = idx >> 2, c4 = idx & 3;
            cp_async16(&As[stg][row*LDT + c4*4],
                       A + (size_t)(bm+row)*K + k0 + c4*4);
        }
        #pragma unroll
        for (int i=0;i<B_F4;i++){
            int idx = tid + i*256;
            int row = idx >> 2, c4 = idx & 3;
            cp_async16(&Bs[stg][row*LDT + c4*4],
                       W + (size_t)(bn+row)*K + k0 + c4*4);
        }
        cp_commit();
    };

    issue_stage(0, 0);

    for (int kt = 0; kt < nK; kt++) {
        if (kt + 1 < nK) { issue_stage((kt+1)&1, kt+1); cp_wait1(); }
        else             { cp_wait0(); }
        __syncthreads();
        int stg = kt & 1;
        #pragma unroll
        for (int kk=0; kk<BK; kk+=8) {
            wmma::fragment<wmma::matrix_a,16,16,8,wmma::precision::tf32,wmma::row_major> af[MF];
            wmma::fragment<wmma::matrix_b,16,16,8,wmma::precision::tf32,wmma::col_major> bf[NF];
            #pragma unroll
            for (int i=0;i<MF;i++){
                wmma::load_matrix_sync(af[i], &As[stg][(wm*WM + i*16)*LDT + kk], LDT);
                #pragma unroll
                for (int e=0;e<af[i].num_elements;e++)
                    af[i].x[e] = wmma::__float_to_tf32(af[i].x[e]);
            }
            #pragma unroll
            for (int j=0;j<NF;j++){
                wmma::load_matrix_sync(bf[j], &Bs[stg][(wn*WN + j*16)*LDT + kk], LDT);
                #pragma unroll
                for (int e=0;e<bf[j].num_elements;e++)
                    bf[j].x[e] = wmma::__float_to_tf32(bf[j].x[e]);
            }
            #pragma unroll
            for (int i=0;i<MF;i++)
                #pragma unroll
                for (int j=0;j<NF;j++)
                    wmma::mma_sync(cf[i][j], af[i], bf[j], cf[i][j]);
        }
        __syncthreads();   // all reads of stg done before it is refilled
    }

    // ---- epilogue ----
    #pragma unroll
    for (int i=0;i<MF;i++){
        #pragma unroll
        for (int j=0;j<NF;j++){
            int r0 = bm + wm*WM + i*16;
            int c0 = bn + wn*WN + j*16;
            if (EPI == 0) {
                wmma::store_matrix_sync(&C[(size_t)r0*N + c0], cf[i][j], N, wmma::mem_row_major);
            } else if (EPI == 1 || EPI == 2) {
                #pragma unroll
                for (int e=0;e<cf[i][j].num_elements;e++){
                    float v = cf[i][j].x[e];
                    if (EPI == 1) { v = fmaxf(v, 0.f); v = v*v; }
                    else          { v = 1.f/(1.f + expf(-v)); }
                    cf[i][j].x[e] = v;
                }
                wmma::store_matrix_sync(&C[(size_t)r0*N + c0], cf[i][j], N, wmma::mem_row_major);
            } else {
                float* buf = &Ep[warp*256];
                wmma::store_matrix_sync(buf, cf[i][j], 16, wmma::mem_row_major);
                __syncwarp();
                #pragma unroll
                for (int e=0;e<8;e++){
                    int idx2 = lane*8 + e;      // 0..255
                    int rr = idx2>>4, cc2 = idx2&15;
                    size_t o = (size_t)(r0+rr)*N + (c0+cc2);
                    float v = buf[idx2];
                    if (EPI == 3) v += Res[o];
                    else          v = fmaf(v, Gate[o], Res[o]);
                    C[o] = v;
                }
                __syncwarp();
            }
        }
    }
}

// ---------------- WKV sequential scan ---------------------------------------
__global__ void wkv_kernel(const float* __restrict__ r, const float* __restrict__ k,
                           const float* __restrict__ v, float* __restrict__ out,
                           const float* __restrict__ bonus, const float* __restrict__ decay)
{
    int blk  = blockIdx.x;          // b*H*2 + h*2 + vs
    int vs   = blk & 1;
    int h    = (blk >> 1) % H_;
    int b    = blk / (2*H_);
    int tid  = threadIdx.x;         // 128
    int kc   = tid & 3;
    int vloc = tid >> 2;            // 0..31
    int vg   = vs*32 + vloc;

    size_t off = (size_t)b*T_*C_ + (size_t)h*K_;
    const float* rp = r + off;
    const float* kp = k + off;
    const float* vp = v + off;
    float*       op = out + off;

    float u[16], w[16], st[16];
    #pragma unroll
    for (int i = 0; i < 16; i++) {
        int kk = kc*16 + i;
        u[i]  = bonus[h*K_ + kk];
        w[i]  = expf(-expf(decay[h*K_ + kk]));
        st[i] = 0.f;
    }

    __shared__ float shr[64], shk[64];

    for (int t = 0; t < T_; t++) {
        __syncthreads();
        if (tid < 64) shr[tid]      = rp[(size_t)t*C_ + tid];
        else          shk[tid - 64] = kp[(size_t)t*C_ + (tid - 64)];
        __syncthreads();
        float vv  = vp[(size_t)t*C_ + vg];
        float acc = 0.f;
        #pragma unroll
        for (int i = 0; i < 16; i++) {
            float kkv = shk[kc*16 + i] * vv;
            acc   = fmaf(shr[kc*16 + i], fmaf(u[i], kkv, st[i]), acc);
            st[i] = fmaf(st[i], w[i], kkv);
        }
        acc += __shfl_xor_sync(0xffffffffu, acc, 1);
        acc += __shfl_xor_sync(0xffffffffu, acc, 2);
        if (kc == 0) op[(size_t)t*C_ + vg] = acc;
    }
}

// ---------------- GroupNorm(H groups of 64) * silu(g) ----------------------
__global__ void gn_silu_kernel(const float* __restrict__ x, const float* __restrict__ g,
                               float* __restrict__ out,
                               const float* __restrict__ s, const float* __restrict__ bb)
{
    int gid  = blockIdx.x*4 + (threadIdx.x >> 5);  // over B*T*H
    int lane = threadIdx.x & 31;
    int h    = gid % H_;
    int row  = gid / H_;

    const float* xp = x + (size_t)row*C_ + h*K_;
    float x0 = xp[lane], x1 = xp[lane+32];
    float sum = x0 + x1;
    #pragma unroll
    for (int o=16;o;o>>=1) sum += __shfl_xor_sync(0xffffffffu, sum, o);
    float m  = sum * (1.f/64.f);
    float d0 = x0-m, d1 = x1-m;
    float sq = d0*d0 + d1*d1;
    #pragma unroll
    for (int o=16;o;o>>=1) sq += __shfl_xor_sync(0xffffffffu, sq, o);
    float rstd = rsqrtf(sq*(1.f/64.f) + 0.00064f);

    int c0 = h*K_ + lane, c1 = c0 + 32;
    float y0 = fmaf(d0*rstd, s[c0], bb[c0]);
    float y1 = fmaf(d1*rstd, s[c1], bb[c1]);

    const float* gp = g + (size_t)row*C_ + h*K_;
    float g0 = gp[lane], g1 = gp[lane+32];
    y0 *= g0 / (1.f + expf(-g0));
    y1 *= g1 / (1.f + expf(-g1));

    float* opp = out + (size_t)row*C_ + h*K_;
    opp[lane]    = y0;
    opp[lane+32] = y1;
}

// ---------------- orchestration --------------------------------------------
extern "C" void kernel_launch(void* const* d_in, const int* in_sizes, int n_in,
                              void* d_out, int out_size)
{
    (void)in_sizes; (void)n_in; (void)out_size;
    const int*   tokens    = (const int*)  d_in[0];
    const float* embed     = (const float*)d_in[1];
    const float* emb_ln_s  = (const float*)d_in[2];
    const float* emb_ln_b  = (const float*)d_in[3];
    const float* tm_ln_s   = (const float*)d_in[4];
    const float* tm_ln_b   = (const float*)d_in[5];
    const float* ts_r      = (const float*)d_in[6];
    const float* ts_k      = (const float*)d_in[7];
    const float* ts_v      = (const float*)d_in[8];
    const float* ts_g      = (const float*)d_in[9];
    const float* W_r       = (const float*)d_in[10];
    const float* W_k       = (const float*)d_in[11];
    const float* W_v       = (const float*)d_in[12];
    const float* W_g       = (const float*)d_in[13];
    const float* W_o       = (const float*)d_in[14];
    const float* bonus     = (const float*)d_in[15];
    const float* decay     = (const float*)d_in[16];
    const float* gn_s      = (const float*)d_in[17];
    const float* gn_b      = (const float*)d_in[18];
    const float* cm_ln_s   = (const float*)d_in[19];
    const float* cm_ln_b   = (const float*)d_in[20];
    const float* cm_ts_in  = (const float*)d_in[21];
    const float* cm_ts_g   = (const float*)d_in[22];
    const float* W_in      = (const float*)d_in[23];
    const float* W_out     = (const float*)d_in[24];
    const float* W_gate    = (const float*)d_in[25];
    const float* head_ln_s = (const float*)d_in[26];
    const float* head_ln_b = (const float*)d_in[27];
    const float* W_unembed = (const float*)d_in[28];

    float *x, *ln, *a, *rkvg, *wkv, *gated, *hid, *gate;
    cudaGetSymbolAddress((void**)&x,     g_x);
    cudaGetSymbolAddress((void**)&ln,    g_ln);
    cudaGetSymbolAddress((void**)&a,     g_a);
    cudaGetSymbolAddress((void**)&rkvg,  g_rkvg);
    cudaGetSymbolAddress((void**)&wkv,   g_wkv);
    cudaGetSymbolAddress((void**)&gated, g_gated);
    cudaGetSymbolAddress((void**)&hid,   g_hid);
    cudaGetSymbolAddress((void**)&gate,  g_gate);

    const int EW_BLOCKS = (M_*C_ + 255)/256;

    // embedding gather + LN
    ln_kernel<<<M_, 256>>>(embed, tokens, x, emb_ln_s, emb_ln_b, 1e-5f);

    for (int l = 0; l < L_; l++) {
        size_t cc = (size_t)l*C_*C_;
        size_t fc = (size_t)l*DFF_*C_;
        size_t oc = (size_t)l*C_*DFF_;
        size_t hk = (size_t)l*H_*K_;

        // ---- time mixer ----
        ln_kernel<<<M_, 256>>>(x, nullptr, ln, tm_ln_s + l*C_, tm_ln_b + l*C_, 1e-5f);
        lerp4_kernel<<<EW_BLOCKS, 256>>>(ln, ts_r + l*C_, ts_k + l*C_,
                                         ts_v + l*C_, ts_g + l*C_, a);
        // r,k,v,g batched in one launch (grid.z = 4)
        tgemm<128,128,0><<<dim3(C_/128, M_/128, 4), 256>>>(
            a, W_r + cc, W_k + cc, W_v + cc, W_g + cc, rkvg,
            nullptr, nullptr, M_, C_, C_);
        wkv_kernel<<<B_*H_*2, 128>>>(rkvg, rkvg + M_*C_, rkvg + 2*M_*C_, wkv,
                                     bonus + hk, decay + hk);
        gn_silu_kernel<<<(M_*H_)/4, 128>>>(wkv, rkvg + 3*M_*C_, gated,
                                           gn_s + l*C_, gn_b + l*C_);
        tgemm<64,64,3><<<dim3(C_/64, M_/64, 1), 256>>>(
            gated, W_o + cc, nullptr, nullptr, nullptr, x,
            x, nullptr, M_, C_, C_);

        // ---- channel mixer ----
        ln_kernel<<<M_, 256>>>(x, nullptr, ln, cm_ln_s + l*C_, cm_ln_b + l*C_, 1e-5f);
        lerp2_kernel<<<EW_BLOCKS, 256>>>(ln, cm_ts_in + l*C_, cm_ts_g + l*C_,
                                         a, a + M_*C_);
        tgemm<128,128,1><<<dim3(DFF_/128, M_/128, 1), 256>>>(
            a, W_in + fc, nullptr, nullptr, nullptr, hid,
            nullptr, nullptr, M_, DFF_, C_);
        tgemm<64,64,2><<<dim3(C_/64, M_/64, 1), 256>>>(
            a + M_*C_, W_gate + cc, nullptr, nullptr, nullptr, gate,
            nullptr, nullptr, M_, C_, C_);
        tgemm<64,64,4><<<dim3(C_/64, M_/64, 1), 256>>>(
            hid, W_out + oc, nullptr, nullptr, nullptr, x,
            x, gate, M_, C_, DFF_);
    }

    // head LN + unembed
    ln_kernel<<<M_, 256>>>(x, nullptr, ln, head_ln_s, head_ln_b, 1e-5f);
    tgemm<128,128,0><<<dim3(V_/128, M_/128, 1), 256>>>(
        ln, W_unembed, nullptr, nullptr, nullptr, (float*)d_out,
        nullptr, nullptr, M_, V_, C_);
}

// round 4
// speedup vs baseline: 1.5349x; 1.1972x over previous
#include <cuda_runtime.h>
#include <math.h>
#include <mma.h>

using namespace nvcuda;

// Problem dims
#define B_   2
#define T_   512
#define C_   768
#define H_   12
#define K_   64
#define L_   6
#define DFF_ 2688
#define V_   50304
#define M_   (B_*T_)   // 1024 rows

// weight family sizes (floats)
#define CCL  (L_*C_*C_)        // 3538944
#define FCL  (L_*DFF_*C_)      // 12386304
#define VCL  (V_*C_)           // 38633472

// offsets into tf32-rounded weight scratch
#define OFF_WR   0
#define OFF_WK   (OFF_WR + CCL)
#define OFF_WV   (OFF_WK + CCL)
#define OFF_WG   (OFF_WV + CCL)
#define OFF_WO   (OFF_WG + CCL)
#define OFF_WIN  (OFF_WO + CCL)
#define OFF_WOUT (OFF_WIN + FCL)
#define OFF_WGT  (OFF_WOUT + FCL)
#define OFF_WUN  (OFF_WGT + CCL)
#define WTF_TOT  (OFF_WUN + VCL)   // 84639744 floats (~339MB)

// ---------------- scratch (device globals; no allocation allowed) ----------
__device__ float g_wtf  [WTF_TOT];   // tf32-rounded weights
__device__ float g_x    [M_*C_];
__device__ float g_ln   [M_*C_];
__device__ float g_a    [4*M_*C_];   // lerp outputs (batched, tf32-rounded)
__device__ float g_rkvg [4*M_*C_];   // r,k,v,g (batched)
__device__ float g_wkv  [M_*C_];
__device__ float g_gated[M_*C_];
__device__ float g_hid  [M_*DFF_];
__device__ float g_gate [M_*C_];

// ---------------- helpers ---------------------------------------------------
__device__ __forceinline__ float tf32r(float x) {
    return wmma::__float_to_tf32(x);
}
__device__ __forceinline__ void cp_async16(void* smem_dst, const void* gsrc) {
    unsigned dst = (unsigned)__cvta_generic_to_shared(smem_dst);
    asm volatile("cp.async.cg.shared.global [%0], [%1], 16;\n" :: "r"(dst), "l"(gsrc));
}
__device__ __forceinline__ void cp_commit() {
    asm volatile("cp.async.commit_group;\n");
}
__device__ __forceinline__ void cp_wait1() {
    asm volatile("cp.async.wait_group 1;\n");
}
__device__ __forceinline__ void cp_wait0() {
    asm volatile("cp.async.wait_group 0;\n");
}

// ---------------- tf32 rounding pass (weights, once per call) --------------
__global__ void cvt_tf32_kernel(const float* __restrict__ src,
                                float* __restrict__ dst, int n4)
{
    int i = blockIdx.x*blockDim.x + threadIdx.x;
    if (i >= n4) return;
    float4 v = ((const float4*)src)[i];
    v.x = tf32r(v.x); v.y = tf32r(v.y); v.z = tf32r(v.z); v.w = tf32r(v.w);
    ((float4*)dst)[i] = v;
}

// ---------------- LayerNorm over C=768 (one block / row, 256 threads) ------
__global__ void ln_kernel(const float* __restrict__ in,
                          const int*   __restrict__ tokens,   // null => direct rows
                          float*       __restrict__ out,
                          const float* __restrict__ s,
                          const float* __restrict__ bia,
                          float eps, int round_out)
{
    int row = blockIdx.x;
    const float* xp = tokens ? (in + (size_t)tokens[row]*C_)
                             : (in + (size_t)row*C_);
    int tid = threadIdx.x;                 // 256
    float v0 = xp[tid], v1 = xp[tid+256], v2 = xp[tid+512];

    __shared__ float red[8];
    __shared__ float s_mean, s_rstd;

    float sum = v0 + v1 + v2;
    #pragma unroll
    for (int o=16;o;o>>=1) sum += __shfl_xor_sync(0xffffffffu, sum, o);
    if ((tid & 31) == 0) red[tid>>5] = sum;
    __syncthreads();
    if (tid == 0) { float t=0.f; for (int i=0;i<8;i++) t += red[i]; s_mean = t*(1.f/C_); }
    __syncthreads();
    float m  = s_mean;
    float d0 = v0-m, d1 = v1-m, d2 = v2-m;
    float sq = d0*d0 + d1*d1 + d2*d2;
    #pragma unroll
    for (int o=16;o;o>>=1) sq += __shfl_xor_sync(0xffffffffu, sq, o);
    __syncthreads();
    if ((tid & 31) == 0) red[tid>>5] = sq;
    __syncthreads();
    if (tid == 0) { float t=0.f; for (int i=0;i<8;i++) t += red[i];
                    s_rstd = rsqrtf(t*(1.f/C_) + eps); }
    __syncthreads();
    float rs = s_rstd;
    float y0 = d0*rs*s[tid]     + bia[tid];
    float y1 = d1*rs*s[tid+256] + bia[tid+256];
    float y2 = d2*rs*s[tid+512] + bia[tid+512];
    if (round_out) { y0 = tf32r(y0); y1 = tf32r(y1); y2 = tf32r(y2); }
    float* op = out + (size_t)row*C_;
    op[tid] = y0; op[tid+256] = y1; op[tid+512] = y2;
}

// ---------------- token-shift + 4-way lerp (time mixer) --------------------
__global__ void lerp4_kernel(const float* __restrict__ ln,
                             const float* __restrict__ tr, const float* __restrict__ tk,
                             const float* __restrict__ tv, const float* __restrict__ tg,
                             float* __restrict__ aout)
{
    int idx = blockIdx.x*blockDim.x + threadIdx.x;
    if (idx >= M_*C_) return;
    int c = idx % C_;
    int t = (idx / C_) % T_;
    float x  = ln[idx];
    float xs = (t == 0) ? 0.f : ln[idx - C_];
    float d  = xs - x;
    aout[idx]            = tf32r(fmaf(tr[c], d, x));
    aout[idx +   M_*C_]  = tf32r(fmaf(tk[c], d, x));
    aout[idx + 2*M_*C_]  = tf32r(fmaf(tv[c], d, x));
    aout[idx + 3*M_*C_]  = tf32r(fmaf(tg[c], d, x));
}

// ---------------- token-shift + 2-way lerp (channel mixer) -----------------
__global__ void lerp2_kernel(const float* __restrict__ ln,
                             const float* __restrict__ ti, const float* __restrict__ tg,
                             float* __restrict__ xi, float* __restrict__ xg)
{
    int idx = blockIdx.x*blockDim.x + threadIdx.x;
    if (idx >= M_*C_) return;
    int c = idx % C_;
    int t = (idx / C_) % T_;
    float x  = ln[idx];
    float xs = (t == 0) ? 0.f : ln[idx - C_];
    float d  = xs - x;
    xi[idx] = tf32r(fmaf(ti[c], d, x));
    xg[idx] = tf32r(fmaf(tg[c], d, x));
}

// ---------------- TF32 tensor-core GEMM, cp.async double-buffered ----------
// Operands are PRE-ROUNDED to tf32 — no in-loop conversion.
// C[M,N] = A[M,K] @ W[N,K]^T + epilogue
// EPI: 0 none | 1 relu()^2 (tf32-rounded out) | 2 sigmoid | 3 +Res | 4 *Gate + Res
template<int BM, int BN, int EPI>
__global__ void __launch_bounds__(256, 2)
tgemm(const float* __restrict__ Abase,
      const float* __restrict__ W0, const float* __restrict__ W1,
      const float* __restrict__ W2, const float* __restrict__ W3,
      float* __restrict__ Cbase,
      const float* __restrict__ Res, const float* __restrict__ Gate,
      int M, int N, int K)
{
    constexpr int BK  = 16;
    constexpr int LDT = 20;                 // 16 + pad (80B rows, 16B aligned)
    __shared__ __align__(16) float As[2][BM*LDT];
    __shared__ __align__(16) float Bs[2][BN*LDT];
    __shared__ __align__(16) float Ep[(EPI >= 3) ? 8*256 : 8];

    int z = blockIdx.z;
    const float* A = Abase + (size_t)z*M*K;
    const float* W = W0;
    if (z == 1) W = W1; else if (z == 2) W = W2; else if (z == 3) W = W3;
    float* C = Cbase + (size_t)z*M*N;

    int bm = blockIdx.y*BM, bn = blockIdx.x*BN;
    int tid = threadIdx.x, warp = tid>>5, lane = tid&31;
    int wm = warp >> 2;           // 0..1
    int wn = warp & 3;            // 0..3
    constexpr int WM = BM/2;
    constexpr int WN = BN/4;
    constexpr int MF = WM/16, NF = WN/16;

    wmma::fragment<wmma::accumulator,16,16,8,float> cf[MF][NF];
    #pragma unroll
    for (int i=0;i<MF;i++)
        #pragma unroll
        for (int j=0;j<NF;j++) wmma::fill_fragment(cf[i][j], 0.f);

    constexpr int A_F4 = BM*(BK/4)/256;
    constexpr int B_F4 = BN*(BK/4)/256;

    const int nK = K / BK;

    auto issue_stage = [&](int stg, int kt) {
        int k0 = kt*BK;
        #pragma unroll
        for (int i=0;i<A_F4;i++){
            int idx = tid + i*256;               // over BM*4 float4
            int row = idx >> 2, c4 = idx & 3;
            cp_async16(&As[stg][row*LDT + c4*4],
                       A + (size_t)(bm+row)*K + k0 + c4*4);
        }
        #pragma unroll
        for (int i=0;i<B_F4;i++){
            int idx = tid + i*256;
            int row = idx >> 2, c4 = idx & 3;
            cp_async16(&Bs[stg][row*LDT + c4*4],
                       W + (size_t)(bn+row)*K + k0 + c4*4);
        }
        cp_commit();
    };

    issue_stage(0, 0);

    for (int kt = 0; kt < nK; kt++) {
        if (kt + 1 < nK) { issue_stage((kt+1)&1, kt+1); cp_wait1(); }
        else             { cp_wait0(); }
        __syncthreads();
        int stg = kt & 1;
        #pragma unroll
        for (int kk=0; kk<BK; kk+=8) {
            wmma::fragment<wmma::matrix_a,16,16,8,wmma::precision::tf32,wmma::row_major> af[MF];
            wmma::fragment<wmma::matrix_b,16,16,8,wmma::precision::tf32,wmma::col_major> bf[NF];
            #pragma unroll
            for (int i=0;i<MF;i++)
                wmma::load_matrix_sync(af[i], &As[stg][(wm*WM + i*16)*LDT + kk], LDT);
            #pragma unroll
            for (int j=0;j<NF;j++)
                wmma::load_matrix_sync(bf[j], &Bs[stg][(wn*WN + j*16)*LDT + kk], LDT);
            #pragma unroll
            for (int i=0;i<MF;i++)
                #pragma unroll
                for (int j=0;j<NF;j++)
                    wmma::mma_sync(cf[i][j], af[i], bf[j], cf[i][j]);
        }
        __syncthreads();   // all reads of stg done before it is refilled
    }

    // ---- epilogue ----
    #pragma unroll
    for (int i=0;i<MF;i++){
        #pragma unroll
        for (int j=0;j<NF;j++){
            int r0 = bm + wm*WM + i*16;
            int c0 = bn + wn*WN + j*16;
            if (EPI == 0) {
                wmma::store_matrix_sync(&C[(size_t)r0*N + c0], cf[i][j], N, wmma::mem_row_major);
            } else if (EPI == 1 || EPI == 2) {
                #pragma unroll
                for (int e=0;e<cf[i][j].num_elements;e++){
                    float v = cf[i][j].x[e];
                    if (EPI == 1) { v = fmaxf(v, 0.f); v = tf32r(v*v); }
                    else          { v = 1.f/(1.f + expf(-v)); }
                    cf[i][j].x[e] = v;
                }
                wmma::store_matrix_sync(&C[(size_t)r0*N + c0], cf[i][j], N, wmma::mem_row_major);
            } else {
                float* buf = &Ep[warp*256];
                wmma::store_matrix_sync(buf, cf[i][j], 16, wmma::mem_row_major);
                __syncwarp();
                #pragma unroll
                for (int e=0;e<8;e++){
                    int idx2 = lane*8 + e;      // 0..255
                    int rr = idx2>>4, cc2 = idx2&15;
                    size_t o = (size_t)(r0+rr)*N + (c0+cc2);
                    float v = buf[idx2];
                    if (EPI == 3) v += Res[o];
                    else          v = fmaf(v, Gate[o], Res[o]);
                    C[o] = v;
                }
                __syncwarp();
            }
        }
    }
}

// ---------------- WKV sequential scan (double-buffered, prefetched) --------
// grid: B*H*2 blocks (v split in halves of 32), 128 threads.
// tid = vloc*4 + kc : 4 lanes split the k-sum (16 k's each), shuffle-reduce.
__global__ void wkv_kernel(const float* __restrict__ r, const float* __restrict__ k,
                           const float* __restrict__ v, float* __restrict__ out,
                           const float* __restrict__ bonus, const float* __restrict__ decay)
{
    int blk  = blockIdx.x;          // b*H*2 + h*2 + vs
    int vs   = blk & 1;
    int h    = (blk >> 1) % H_;
    int b    = blk / (2*H_);
    int tid  = threadIdx.x;         // 128
    int kc   = tid & 3;
    int vloc = tid >> 2;            // 0..31
    int vg   = vs*32 + vloc;

    size_t off = (size_t)b*T_*C_ + (size_t)h*K_;
    const float* rp = r + off;
    const float* kp = k + off;
    const float* vp = v + off;
    float*       op = out + off;

    float u[16], w[16], st[16];
    #pragma unroll
    for (int i = 0; i < 16; i++) {
        int kk = kc*16 + i;
        u[i]  = bonus[h*K_ + kk];
        w[i]  = expf(-expf(decay[h*K_ + kk]));
        st[i] = 0.f;
    }

    __shared__ float shr[2][64], shk[2][64];

    // preload t = 0
    if (tid < 64) shr[0][tid]      = rp[tid];
    else          shk[0][tid - 64] = kp[tid - 64];
    float vv = vp[vg];
    __syncthreads();

    for (int t = 0; t < T_; t++) {
        int cur = t & 1, nxt = cur ^ 1;

        // prefetch t+1 into registers (hidden behind compute)
        float nr = 0.f, nk = 0.f, nv = 0.f;
        if (t + 1 < T_) {
            size_t o1 = (size_t)(t+1)*C_;
            if (tid < 64) nr = rp[o1 + tid];
            else          nk = kp[o1 + tid - 64];
            nv = vp[o1 + vg];
        }

        float acc0 = 0.f, acc1 = 0.f;
        #pragma unroll
        for (int i = 0; i < 16; i += 2) {
            float k0 = shk[cur][kc*16 + i]     * vv;
            float k1 = shk[cur][kc*16 + i + 1] * vv;
            acc0  = fmaf(shr[cur][kc*16 + i],     fmaf(u[i],   k0, st[i]),   acc0);
            acc1  = fmaf(shr[cur][kc*16 + i + 1], fmaf(u[i+1], k1, st[i+1]), acc1);
            st[i]   = fmaf(st[i],   w[i],   k0);
            st[i+1] = fmaf(st[i+1], w[i+1], k1);
        }
        float acc = acc0 + acc1;
        acc += __shfl_xor_sync(0xffffffffu, acc, 1);
        acc += __shfl_xor_sync(0xffffffffu, acc, 2);
        if (kc == 0) op[(size_t)t*C_ + vg] = acc;

        if (t + 1 < T_) {
            if (tid < 64) shr[nxt][tid]      = nr;
            else          shk[nxt][tid - 64] = nk;
        }
        vv = nv;
        __syncthreads();
    }
}

// ---------------- GroupNorm(H groups of 64) * silu(g), tf32-rounded out ----
__global__ void gn_silu_kernel(const float* __restrict__ x, const float* __restrict__ g,
                               float* __restrict__ out,
                               const float* __restrict__ s, const float* __restrict__ bb)
{
    int gid  = blockIdx.x*4 + (threadIdx.x >> 5);  // over B*T*H
    int lane = threadIdx.x & 31;
    int h    = gid % H_;
    int row  = gid / H_;

    const float* xp = x + (size_t)row*C_ + h*K_;
    float x0 = xp[lane], x1 = xp[lane+32];
    float sum = x0 + x1;
    #pragma unroll
    for (int o=16;o;o>>=1) sum += __shfl_xor_sync(0xffffffffu, sum, o);
    float m  = sum * (1.f/64.f);
    float d0 = x0-m, d1 = x1-m;
    float sq = d0*d0 + d1*d1;
    #pragma unroll
    for (int o=16;o;o>>=1) sq += __shfl_xor_sync(0xffffffffu, sq, o);
    float rstd = rsqrtf(sq*(1.f/64.f) + 0.00064f);

    int c0 = h*K_ + lane, c1 = c0 + 32;
    float y0 = fmaf(d0*rstd, s[c0], bb[c0]);
    float y1 = fmaf(d1*rstd, s[c1], bb[c1]);

    const float* gp = g + (size_t)row*C_ + h*K_;
    float g0 = gp[lane], g1 = gp[lane+32];
    y0 *= g0 / (1.f + expf(-g0));
    y1 *= g1 / (1.f + expf(-g1));

    float* opp = out + (size_t)row*C_ + h*K_;
    opp[lane]    = tf32r(y0);
    opp[lane+32] = tf32r(y1);
}

// ---------------- orchestration --------------------------------------------
extern "C" void kernel_launch(void* const* d_in, const int* in_sizes, int n_in,
                              void* d_out, int out_size)
{
    (void)in_sizes; (void)n_in; (void)out_size;
    const int*   tokens    = (const int*)  d_in[0];
    const float* embed     = (const float*)d_in[1];
    const float* emb_ln_s  = (const float*)d_in[2];
    const float* emb_ln_b  = (const float*)d_in[3];
    const float* tm_ln_s   = (const float*)d_in[4];
    const float* tm_ln_b   = (const float*)d_in[5];
    const float* ts_r      = (const float*)d_in[6];
    const float* ts_k      = (const float*)d_in[7];
    const float* ts_v      = (const float*)d_in[8];
    const float* ts_g      = (const float*)d_in[9];
    const float* W_r       = (const float*)d_in[10];
    const float* W_k       = (const float*)d_in[11];
    const float* W_v       = (const float*)d_in[12];
    const float* W_g       = (const float*)d_in[13];
    const float* W_o       = (const float*)d_in[14];
    const float* bonus     = (const float*)d_in[15];
    const float* decay     = (const float*)d_in[16];
    const float* gn_s      = (const float*)d_in[17];
    const float* gn_b      = (const float*)d_in[18];
    const float* cm_ln_s   = (const float*)d_in[19];
    const float* cm_ln_b   = (const float*)d_in[20];
    const float* cm_ts_in  = (const float*)d_in[21];
    const float* cm_ts_g   = (const float*)d_in[22];
    const float* W_in      = (const float*)d_in[23];
    const float* W_out     = (const float*)d_in[24];
    const float* W_gate    = (const float*)d_in[25];
    const float* head_ln_s = (const float*)d_in[26];
    const float* head_ln_b = (const float*)d_in[27];
    const float* W_unembed = (const float*)d_in[28];

    float *wtf, *x, *ln, *a, *rkvg, *wkv, *gated, *hid, *gate;
    cudaGetSymbolAddress((void**)&wtf,   g_wtf);
    cudaGetSymbolAddress((void**)&x,     g_x);
    cudaGetSymbolAddress((void**)&ln,    g_ln);
    cudaGetSymbolAddress((void**)&a,     g_a);
    cudaGetSymbolAddress((void**)&rkvg,  g_rkvg);
    cudaGetSymbolAddress((void**)&wkv,   g_wkv);
    cudaGetSymbolAddress((void**)&gated, g_gated);
    cudaGetSymbolAddress((void**)&hid,   g_hid);
    cudaGetSymbolAddress((void**)&gate,  g_gate);

    // ---- one-pass tf32 rounding of all weights into scratch ----
    auto cvt = [&](const float* src, float* dst, long n) {
        int n4 = (int)(n/4);
        cvt_tf32_kernel<<<(n4 + 255)/256, 256>>>(src, dst, n4);
    };
    cvt(W_r,       wtf + OFF_WR,   CCL);
    cvt(W_k,       wtf + OFF_WK,   CCL);
    cvt(W_v,       wtf + OFF_WV,   CCL);
    cvt(W_g,       wtf + OFF_WG,   CCL);
    cvt(W_o,       wtf + OFF_WO,   CCL);
    cvt(W_in,      wtf + OFF_WIN,  FCL);
    cvt(W_out,     wtf + OFF_WOUT, FCL);
    cvt(W_gate,    wtf + OFF_WGT,  CCL);
    cvt(W_unembed, wtf + OFF_WUN,  VCL);

    const float* cW_r  = wtf + OFF_WR;
    const float* cW_k  = wtf + OFF_WK;
    const float* cW_v  = wtf + OFF_WV;
    const float* cW_g  = wtf + OFF_WG;
    const float* cW_o  = wtf + OFF_WO;
    const float* cW_in = wtf + OFF_WIN;
    const float* cW_out= wtf + OFF_WOUT;
    const float* cW_gt = wtf + OFF_WGT;
    const float* cW_un = wtf + OFF_WUN;

    const int EW_BLOCKS = (M_*C_ + 255)/256;

    // embedding gather + LN (residual base: keep fp32)
    ln_kernel<<<M_, 256>>>(embed, tokens, x, emb_ln_s, emb_ln_b, 1e-5f, 0);

    for (int l = 0; l < L_; l++) {
        size_t cc = (size_t)l*C_*C_;
        size_t fc = (size_t)l*DFF_*C_;
        size_t oc = (size_t)l*C_*DFF_;
        size_t hk = (size_t)l*H_*K_;

        // ---- time mixer ----
        ln_kernel<<<M_, 256>>>(x, nullptr, ln, tm_ln_s + l*C_, tm_ln_b + l*C_, 1e-5f, 0);
        lerp4_kernel<<<EW_BLOCKS, 256>>>(ln, ts_r + l*C_, ts_k + l*C_,
                                         ts_v + l*C_, ts_g + l*C_, a);
        tgemm<128,128,0><<<dim3(C_/128, M_/128, 4), 256>>>(
            a, cW_r + cc, cW_k + cc, cW_v + cc, cW_g + cc, rkvg,
            nullptr, nullptr, M_, C_, C_);
        wkv_kernel<<<B_*H_*2, 128>>>(rkvg, rkvg + M_*C_, rkvg + 2*M_*C_, wkv,
                                     bonus + hk, decay + hk);
        gn_silu_kernel<<<(M_*H_)/4, 128>>>(wkv, rkvg + 3*M_*C_, gated,
                                           gn_s + l*C_, gn_b + l*C_);
        tgemm<64,64,3><<<dim3(C_/64, M_/64, 1), 256>>>(
            gated, cW_o + cc, nullptr, nullptr, nullptr, x,
            x, nullptr, M_, C_, C_);

        // ---- channel mixer ----
        ln_kernel<<<M_, 256>>>(x, nullptr, ln, cm_ln_s + l*C_, cm_ln_b + l*C_, 1e-5f, 0);
        lerp2_kernel<<<EW_BLOCKS, 256>>>(ln, cm_ts_in + l*C_, cm_ts_g + l*C_,
                                         a, a + M_*C_);
        tgemm<128,128,1><<<dim3(DFF_/128, M_/128, 1), 256>>>(
            a, cW_in + fc, nullptr, nullptr, nullptr, hid,
            nullptr, nullptr, M_, DFF_, C_);
        tgemm<64,64,2><<<dim3(C_/64, M_/64, 1), 256>>>(
            a + M_*C_, cW_gt + cc, nullptr, nullptr, nullptr, gate,
            nullptr, nullptr, M_, C_, C_);
        tgemm<64,64,4><<<dim3(C_/64, M_/64, 1), 256>>>(
            hid, cW_out + oc, nullptr, nullptr, nullptr, x,
            x, gate, M_, C_, DFF_);
    }

    // head LN (tf32-rounded: feeds unembed GEMM) + unembed
    ln_kernel<<<M_, 256>>>(x, nullptr, ln, head_ln_s, head_ln_b, 1e-5f, 1);
    tgemm<128,128,0><<<dim3(V_/128, M_/128, 1), 256>>>(
        ln, cW_un, nullptr, nullptr, nullptr, (float*)d_out,
        nullptr, nullptr, M_, V_, C_);
}

// round 6
// speedup vs baseline: 1.6545x; 1.0779x over previous
#include <cuda_runtime.h>
#include <math.h>
#include <mma.h>
#include <cstdint>

using namespace nvcuda;

// Problem dims
#define B_   2
#define T_   512
#define C_   768
#define H_   12
#define K_   64
#define L_   6
#define DFF_ 2688
#define V_   50304
#define M_   (B_*T_)   // 1024 rows

// weight family sizes (floats)
#define CCL  (L_*C_*C_)
#define FCL  (L_*DFF_*C_)
#define VCL  (V_*C_)

#define OFF_WR   0
#define OFF_WK   (OFF_WR + CCL)
#define OFF_WV   (OFF_WK + CCL)
#define OFF_WG   (OFF_WV + CCL)
#define OFF_WO   (OFF_WG + CCL)
#define OFF_WIN  (OFF_WO + CCL)
#define OFF_WOUT (OFF_WIN + FCL)
#define OFF_WGT  (OFF_WOUT + FCL)
#define OFF_WUN  (OFF_WGT + CCL)
#define WTF_TOT  (OFF_WUN + VCL)

// ---------------- scratch (device globals; no allocation allowed) ----------
__device__ float g_wtf  [WTF_TOT];   // tf32-rounded weights
__device__ float g_x    [M_*C_];
__device__ float g_ln   [M_*C_];
__device__ float g_a    [4*M_*C_];   // lerp outputs; reused as split-K partials
__device__ float g_rkvg [4*M_*C_];
__device__ float g_wkv  [M_*C_];
__device__ float g_gated[M_*C_];
__device__ float g_hid  [M_*DFF_];
__device__ float g_gate [M_*C_];

// ---------------- helpers ---------------------------------------------------
__device__ __forceinline__ float tf32r(float x) { return wmma::__float_to_tf32(x); }

__device__ __forceinline__ void cp_async16(void* smem_dst, const void* gsrc) {
    unsigned dst = (unsigned)__cvta_generic_to_shared(smem_dst);
    asm volatile("cp.async.cg.shared.global [%0], [%1], 16;\n" :: "r"(dst), "l"(gsrc));
}
__device__ __forceinline__ void cp_commit() { asm volatile("cp.async.commit_group;\n"); }
__device__ __forceinline__ void cp_wait1()  { asm volatile("cp.async.wait_group 1;\n"); }
__device__ __forceinline__ void cp_wait0()  { asm volatile("cp.async.wait_group 0;\n"); }

// ---------------- tf32 rounding pass (weights, once per call) --------------
__global__ void cvt_tf32_kernel(const float* __restrict__ src,
                                float* __restrict__ dst, int n4)
{
    int i = blockIdx.x*blockDim.x + threadIdx.x;
    if (i >= n4) return;
    float4 v = ((const float4*)src)[i];
    v.x = tf32r(v.x); v.y = tf32r(v.y); v.z = tf32r(v.z); v.w = tf32r(v.w);
    ((float4*)dst)[i] = v;
}

// ---------------- TF32 wmma GEMM, BK=32, cp.async double-buffered ----------
// C[M,N] = A[M,K(seg)] @ W[N,K(seg)]^T (+ epilogue). Operands pre-rounded tf32.
// EPI: 0 none | 1 relu()^2 tf32 | 2 sigmoid | 3 +Res | 4 *Gate+Res
// SPLITK=0: grid.z selects weight among W0..W3 (A/C strided by M*lda / M*N).
// SPLITK=1: grid.z = K-segment index; A/W offset by z*Kseg cols; C -> partial z.
template<int BM, int BN, int WARPS, int EPI, int SPLITK>
__global__ void __launch_bounds__(WARPS*32, (WARPS==8)?2:4)
tgemm(const float* __restrict__ Abase,
      const float* __restrict__ W0, const float* __restrict__ W1,
      const float* __restrict__ W2, const float* __restrict__ W3,
      float* __restrict__ Cbase,
      const float* __restrict__ Res, const float* __restrict__ Gate,
      int M, int N, int Kseg, int lda)
{
    constexpr int NT  = WARPS*32;
    constexpr int BK  = 32;
    constexpr int LDT = 36;
    extern __shared__ __align__(16) float sh[];
    float* As = sh;                          // [2][BM*LDT]
    float* Bs = sh + 2*BM*LDT;               // [2][BN*LDT]
    __shared__ __align__(16) float Ep[(EPI >= 3) ? WARPS*256 : 8];

    int z = blockIdx.z;
    const float* A;
    const float* W;
    float* C;
    if (SPLITK) {
        A = Abase + (size_t)z*Kseg;
        W = W0    + (size_t)z*Kseg;
        C = Cbase + (size_t)z*M*N;
    } else {
        A = Abase + (size_t)z*M*lda;
        W = W0;
        if (z == 1) W = W1; else if (z == 2) W = W2; else if (z == 3) W = W3;
        C = Cbase + (size_t)z*M*N;
    }

    int bm = blockIdx.y*BM, bn = blockIdx.x*BN;
    int tid = threadIdx.x, warp = tid>>5, lane = tid&31;
    constexpr int WC = (WARPS == 8) ? 4 : 2;      // warps along N
    int wm = warp / WC;                            // 0..1
    int wn = warp % WC;
    constexpr int WM = BM/2;
    constexpr int WN = BN/WC;
    constexpr int MF = WM/16, NF = WN/16;

    wmma::fragment<wmma::accumulator,16,16,8,float> cf[MF][NF];
    #pragma unroll
    for (int i=0;i<MF;i++)
        #pragma unroll
        for (int j=0;j<NF;j++) wmma::fill_fragment(cf[i][j], 0.f);

    constexpr int A_F4 = BM*(BK/4)/NT;   // = 4
    constexpr int B_F4 = BN*(BK/4)/NT;   // = 4

    const int nK = Kseg / BK;

    auto issue_stage = [&](int stg, int kt) {
        int k0 = kt*BK;
        float* as = As + stg*BM*LDT;
        float* bs = Bs + stg*BN*LDT;
        #pragma unroll
        for (int i=0;i<A_F4;i++){
            int idx = tid + i*NT;                 // over BM*8 float4
            int row = idx >> 3, c4 = idx & 7;
            cp_async16(&as[row*LDT + c4*4],
                       A + (size_t)(bm+row)*lda + k0 + c4*4);
        }
        #pragma unroll
        for (int i=0;i<B_F4;i++){
            int idx = tid + i*NT;
            int row = idx >> 3, c4 = idx & 7;
            cp_async16(&bs[row*LDT + c4*4],
                       W + (size_t)(bn+row)*lda + k0 + c4*4);
        }
        cp_commit();
    };

    issue_stage(0, 0);

    for (int kt = 0; kt < nK; kt++) {
        if (kt + 1 < nK) { issue_stage((kt+1)&1, kt+1); cp_wait1(); }
        else             { cp_wait0(); }
        __syncthreads();
        int stg = kt & 1;
        const float* as = As + stg*BM*LDT;
        const float* bs = Bs + stg*BN*LDT;
        #pragma unroll
        for (int kk=0; kk<BK; kk+=8) {
            wmma::fragment<wmma::matrix_a,16,16,8,wmma::precision::tf32,wmma::row_major> af[MF];
            wmma::fragment<wmma::matrix_b,16,16,8,wmma::precision::tf32,wmma::col_major> bf[NF];
            #pragma unroll
            for (int i=0;i<MF;i++)
                wmma::load_matrix_sync(af[i], &as[(wm*WM + i*16)*LDT + kk], LDT);
            #pragma unroll
            for (int j=0;j<NF;j++)
                wmma::load_matrix_sync(bf[j], &bs[(wn*WN + j*16)*LDT + kk], LDT);
            #pragma unroll
            for (int i=0;i<MF;i++)
                #pragma unroll
                for (int j=0;j<NF;j++)
                    wmma::mma_sync(cf[i][j], af[i], bf[j], cf[i][j]);
        }
        __syncthreads();
    }

    // ---- epilogue ----
    #pragma unroll
    for (int i=0;i<MF;i++){
        #pragma unroll
        for (int j=0;j<NF;j++){
            int r0 = bm + wm*WM + i*16;
            int c0 = bn + wn*WN + j*16;
            if (EPI == 0) {
                wmma::store_matrix_sync(&C[(size_t)r0*N + c0], cf[i][j], N, wmma::mem_row_major);
            } else if (EPI == 1 || EPI == 2) {
                #pragma unroll
                for (int e=0;e<cf[i][j].num_elements;e++){
                    float v = cf[i][j].x[e];
                    if (EPI == 1) { v = fmaxf(v, 0.f); v = tf32r(v*v); }
                    else          { v = 1.f/(1.f + expf(-v)); }
                    cf[i][j].x[e] = v;
                }
                wmma::store_matrix_sync(&C[(size_t)r0*N + c0], cf[i][j], N, wmma::mem_row_major);
            } else {
                float* buf = &Ep[warp*256];
                wmma::store_matrix_sync(buf, cf[i][j], 16, wmma::mem_row_major);
                __syncwarp();
                #pragma unroll
                for (int e=0;e<8;e++){
                    int idx2 = lane*8 + e;
                    int rr = idx2>>4, cc2 = idx2&15;
                    size_t o = (size_t)(r0+rr)*N + (c0+cc2);
                    float v = buf[idx2];
                    if (EPI == 3) v += Res[o];
                    else          v = fmaf(v, Gate[o], Res[o]);
                    C[o] = v;
                }
                __syncwarp();
            }
        }
    }
}

// ---------------- split-K reduce: x += (p0+p1+p2+p3) * gate ----------------
__global__ void reduce4_gate_kernel(const float* __restrict__ parts,
                                    const float* __restrict__ gate,
                                    float* __restrict__ x, int n)
{
    int idx = blockIdx.x*blockDim.x + threadIdx.x;
    if (idx >= n) return;
    float v = (parts[idx]         + parts[idx +   (size_t)n])
            + (parts[idx + 2*(size_t)n] + parts[idx + 3*(size_t)n]);
    x[idx] = fmaf(v, gate[idx], x[idx]);
}

// ---------------- LayerNorm over C=768 (one block / row, 256 threads) ------
__global__ void ln_kernel(const float* __restrict__ in,
                          const int*   __restrict__ tokens,
                          float*       __restrict__ out,
                          const float* __restrict__ s,
                          const float* __restrict__ bia,
                          float eps, int round_out)
{
    int row = blockIdx.x;
    const float* xp = tokens ? (in + (size_t)tokens[row]*C_)
                             : (in + (size_t)row*C_);
    int tid = threadIdx.x;
    float v0 = xp[tid], v1 = xp[tid+256], v2 = xp[tid+512];

    __shared__ float red[8];
    __shared__ float s_mean, s_rstd;

    float sum = v0 + v1 + v2;
    #pragma unroll
    for (int o=16;o;o>>=1) sum += __shfl_xor_sync(0xffffffffu, sum, o);
    if ((tid & 31) == 0) red[tid>>5] = sum;
    __syncthreads();
    if (tid == 0) { float t=0.f; for (int i=0;i<8;i++) t += red[i]; s_mean = t*(1.f/C_); }
    __syncthreads();
    float m  = s_mean;
    float d0 = v0-m, d1 = v1-m, d2 = v2-m;
    float sq = d0*d0 + d1*d1 + d2*d2;
    #pragma unroll
    for (int o=16;o;o>>=1) sq += __shfl_xor_sync(0xffffffffu, sq, o);
    __syncthreads();
    if ((tid & 31) == 0) red[tid>>5] = sq;
    __syncthreads();
    if (tid == 0) { float t=0.f; for (int i=0;i<8;i++) t += red[i];
                    s_rstd = rsqrtf(t*(1.f/C_) + eps); }
    __syncthreads();
    float rs = s_rstd;
    float y0 = d0*rs*s[tid]     + bia[tid];
    float y1 = d1*rs*s[tid+256] + bia[tid+256];
    float y2 = d2*rs*s[tid+512] + bia[tid+512];
    if (round_out) { y0 = tf32r(y0); y1 = tf32r(y1); y2 = tf32r(y2); }
    float* op = out + (size_t)row*C_;
    op[tid] = y0; op[tid+256] = y1; op[tid+512] = y2;
}

// ---------------- token-shift + 4-way lerp (time mixer) --------------------
__global__ void lerp4_kernel(const float* __restrict__ ln,
                             const float* __restrict__ tr, const float* __restrict__ tk,
                             const float* __restrict__ tv, const float* __restrict__ tg,
                             float* __restrict__ aout)
{
    int idx = blockIdx.x*blockDim.x + threadIdx.x;
    if (idx >= M_*C_) return;
    int c = idx % C_;
    int t = (idx / C_) % T_;
    float x  = ln[idx];
    float xs = (t == 0) ? 0.f : ln[idx - C_];
    float d  = xs - x;
    aout[idx]            = tf32r(fmaf(tr[c], d, x));
    aout[idx +   M_*C_]  = tf32r(fmaf(tk[c], d, x));
    aout[idx + 2*M_*C_]  = tf32r(fmaf(tv[c], d, x));
    aout[idx + 3*M_*C_]  = tf32r(fmaf(tg[c], d, x));
}

// ---------------- token-shift + 2-way lerp (channel mixer) -----------------
__global__ void lerp2_kernel(const float* __restrict__ ln,
                             const float* __restrict__ ti, const float* __restrict__ tg,
                             float* __restrict__ xi, float* __restrict__ xg)
{
    int idx = blockIdx.x*blockDim.x + threadIdx.x;
    if (idx >= M_*C_) return;
    int c = idx % C_;
    int t = (idx / C_) % T_;
    float x  = ln[idx];
    float xs = (t == 0) ? 0.f : ln[idx - C_];
    float d  = xs - x;
    xi[idx] = tf32r(fmaf(ti[c], d, x));
    xg[idx] = tf32r(fmaf(tg[c], d, x));
}

// ---------------- WKV sequential scan (double-buffered, prefetched) --------
__global__ void wkv_kernel(const float* __restrict__ r, const float* __restrict__ k,
                           const float* __restrict__ v, float* __restrict__ out,
                           const float* __restrict__ bonus, const float* __restrict__ decay)
{
    int blk  = blockIdx.x;
    int vs   = blk & 1;
    int h    = (blk >> 1) % H_;
    int b    = blk / (2*H_);
    int tid  = threadIdx.x;
    int kc   = tid & 3;
    int vloc = tid >> 2;
    int vg   = vs*32 + vloc;

    size_t off = (size_t)b*T_*C_ + (size_t)h*K_;
    const float* rp = r + off;
    const float* kp = k + off;
    const float* vp = v + off;
    float*       op = out + off;

    float u[16], w[16], st[16];
    #pragma unroll
    for (int i = 0; i < 16; i++) {
        int kk = kc*16 + i;
        u[i]  = bonus[h*K_ + kk];
        w[i]  = expf(-expf(decay[h*K_ + kk]));
        st[i] = 0.f;
    }

    __shared__ float shr[2][64], shk[2][64];

    if (tid < 64) shr[0][tid]      = rp[tid];
    else          shk[0][tid - 64] = kp[tid - 64];
    float vv = vp[vg];
    __syncthreads();

    for (int t = 0; t < T_; t++) {
        int cur = t & 1, nxt = cur ^ 1;

        float nr = 0.f, nk = 0.f, nv = 0.f;
        if (t + 1 < T_) {
            size_t o1 = (size_t)(t+1)*C_;
            if (tid < 64) nr = rp[o1 + tid];
            else          nk = kp[o1 + tid - 64];
            nv = vp[o1 + vg];
        }

        float acc0 = 0.f, acc1 = 0.f;
        #pragma unroll
        for (int i = 0; i < 16; i += 2) {
            float k0 = shk[cur][kc*16 + i]     * vv;
            float k1 = shk[cur][kc*16 + i + 1] * vv;
            acc0  = fmaf(shr[cur][kc*16 + i],     fmaf(u[i],   k0, st[i]),   acc0);
            acc1  = fmaf(shr[cur][kc*16 + i + 1], fmaf(u[i+1], k1, st[i+1]), acc1);
            st[i]   = fmaf(st[i],   w[i],   k0);
            st[i+1] = fmaf(st[i+1], w[i+1], k1);
        }
        float acc = acc0 + acc1;
        acc += __shfl_xor_sync(0xffffffffu, acc, 1);
        acc += __shfl_xor_sync(0xffffffffu, acc, 2);
        if (kc == 0) op[(size_t)t*C_ + vg] = acc;

        if (t + 1 < T_) {
            if (tid < 64) shr[nxt][tid]      = nr;
            else          shk[nxt][tid - 64] = nk;
        }
        vv = nv;
        __syncthreads();
    }
}

// ---------------- GroupNorm(H groups of 64) * silu(g), tf32-rounded out ----
__global__ void gn_silu_kernel(const float* __restrict__ x, const float* __restrict__ g,
                               float* __restrict__ out,
                               const float* __restrict__ s, const float* __restrict__ bb)
{
    int gid  = blockIdx.x*4 + (threadIdx.x >> 5);
    int lane = threadIdx.x & 31;
    int h    = gid % H_;
    int row  = gid / H_;

    const float* xp = x + (size_t)row*C_ + h*K_;
    float x0 = xp[lane], x1 = xp[lane+32];
    float sum = x0 + x1;
    #pragma unroll
    for (int o=16;o;o>>=1) sum += __shfl_xor_sync(0xffffffffu, sum, o);
    float m  = sum * (1.f/64.f);
    float d0 = x0-m, d1 = x1-m;
    float sq = d0*d0 + d1*d1;
    #pragma unroll
    for (int o=16;o;o>>=1) sq += __shfl_xor_sync(0xffffffffu, sq, o);
    float rstd = rsqrtf(sq*(1.f/64.f) + 0.00064f);

    int c0 = h*K_ + lane, c1 = c0 + 32;
    float y0 = fmaf(d0*rstd, s[c0], bb[c0]);
    float y1 = fmaf(d1*rstd, s[c1], bb[c1]);

    const float* gp = g + (size_t)row*C_ + h*K_;
    float g0 = gp[lane], g1 = gp[lane+32];
    y0 *= g0 / (1.f + expf(-g0));
    y1 *= g1 / (1.f + expf(-g1));

    float* opp = out + (size_t)row*C_ + h*K_;
    opp[lane]    = tf32r(y0);
    opp[lane+32] = tf32r(y1);
}

// ---------------- orchestration --------------------------------------------
#define SMEM_BIG   (2*(128+128)*36*4)    // 73728
#define SMEM_SMALL (2*(64+64)*36*4)      // 36864

extern "C" void kernel_launch(void* const* d_in, const int* in_sizes, int n_in,
                              void* d_out, int out_size)
{
    (void)in_sizes; (void)n_in; (void)out_size;
    const int*   tokens    = (const int*)  d_in[0];
    const float* embed     = (const float*)d_in[1];
    const float* emb_ln_s  = (const float*)d_in[2];
    const float* emb_ln_b  = (const float*)d_in[3];
    const float* tm_ln_s   = (const float*)d_in[4];
    const float* tm_ln_b   = (const float*)d_in[5];
    const float* ts_r      = (const float*)d_in[6];
    const float* ts_k      = (const float*)d_in[7];
    const float* ts_v      = (const float*)d_in[8];
    const float* ts_g      = (const float*)d_in[9];
    const float* W_r       = (const float*)d_in[10];
    const float* W_k       = (const float*)d_in[11];
    const float* W_v       = (const float*)d_in[12];
    const float* W_g       = (const float*)d_in[13];
    const float* W_o       = (const float*)d_in[14];
    const float* bonus     = (const float*)d_in[15];
    const float* decay     = (const float*)d_in[16];
    const float* gn_s      = (const float*)d_in[17];
    const float* gn_b      = (const float*)d_in[18];
    const float* cm_ln_s   = (const float*)d_in[19];
    const float* cm_ln_b   = (const float*)d_in[20];
    const float* cm_ts_in  = (const float*)d_in[21];
    const float* cm_ts_g   = (const float*)d_in[22];
    const float* W_in      = (const float*)d_in[23];
    const float* W_out     = (const float*)d_in[24];
    const float* W_gate    = (const float*)d_in[25];
    const float* head_ln_s = (const float*)d_in[26];
    const float* head_ln_b = (const float*)d_in[27];
    const float* W_unembed = (const float*)d_in[28];

    float *wtf, *x, *ln, *a, *rkvg, *wkv, *gated, *hid, *gate;
    cudaGetSymbolAddress((void**)&wtf,   g_wtf);
    cudaGetSymbolAddress((void**)&x,     g_x);
    cudaGetSymbolAddress((void**)&ln,    g_ln);
    cudaGetSymbolAddress((void**)&a,     g_a);
    cudaGetSymbolAddress((void**)&rkvg,  g_rkvg);
    cudaGetSymbolAddress((void**)&wkv,   g_wkv);
    cudaGetSymbolAddress((void**)&gated, g_gated);
    cudaGetSymbolAddress((void**)&hid,   g_hid);
    cudaGetSymbolAddress((void**)&gate,  g_gate);

    // opt-in dynamic smem (idempotent)
    cudaFuncSetAttribute(tgemm<128,128,8,0,0>, cudaFuncAttributeMaxDynamicSharedMemorySize, SMEM_BIG);
    cudaFuncSetAttribute(tgemm<128,128,8,1,0>, cudaFuncAttributeMaxDynamicSharedMemorySize, SMEM_BIG);
    cudaFuncSetAttribute(tgemm<64,64,4,2,0>,   cudaFuncAttributeMaxDynamicSharedMemorySize, SMEM_SMALL);
    cudaFuncSetAttribute(tgemm<64,64,4,3,0>,   cudaFuncAttributeMaxDynamicSharedMemorySize, SMEM_SMALL);
    cudaFuncSetAttribute(tgemm<64,64,4,0,1>,   cudaFuncAttributeMaxDynamicSharedMemorySize, SMEM_SMALL);

    // ---- one-pass tf32 rounding of all weights ----
    auto cvt = [&](const float* src, float* dst, long n) {
        int n4 = (int)(n/4);
        cvt_tf32_kernel<<<(n4 + 255)/256, 256>>>(src, dst, n4);
    };
    cvt(W_r,       wtf + OFF_WR,   CCL);
    cvt(W_k,       wtf + OFF_WK,   CCL);
    cvt(W_v,       wtf + OFF_WV,   CCL);
    cvt(W_g,       wtf + OFF_WG,   CCL);
    cvt(W_o,       wtf + OFF_WO,   CCL);
    cvt(W_in,      wtf + OFF_WIN,  FCL);
    cvt(W_out,     wtf + OFF_WOUT, FCL);
    cvt(W_gate,    wtf + OFF_WGT,  CCL);
    cvt(W_unembed, wtf + OFF_WUN,  VCL);

    const float* cW_r  = wtf + OFF_WR;
    const float* cW_k  = wtf + OFF_WK;
    const float* cW_v  = wtf + OFF_WV;
    const float* cW_g  = wtf + OFF_WG;
    const float* cW_o  = wtf + OFF_WO;
    const float* cW_in = wtf + OFF_WIN;
    const float* cW_out= wtf + OFF_WOUT;
    const float* cW_gt = wtf + OFF_WGT;
    const float* cW_un = wtf + OFF_WUN;

    const int EW_BLOCKS = (M_*C_ + 255)/256;

    ln_kernel<<<M_, 256>>>(embed, tokens, x, emb_ln_s, emb_ln_b, 1e-5f, 0);

    for (int l = 0; l < L_; l++) {
        size_t cc = (size_t)l*C_*C_;
        size_t fc = (size_t)l*DFF_*C_;
        size_t oc = (size_t)l*C_*DFF_;
        size_t hk = (size_t)l*H_*K_;

        // ---- time mixer ----
        ln_kernel<<<M_, 256>>>(x, nullptr, ln, tm_ln_s + l*C_, tm_ln_b + l*C_, 1e-5f, 0);
        lerp4_kernel<<<EW_BLOCKS, 256>>>(ln, ts_r + l*C_, ts_k + l*C_,
                                         ts_v + l*C_, ts_g + l*C_, a);
        tgemm<128,128,8,0,0><<<dim3(C_/128, M_/128, 4), 256, SMEM_BIG>>>(
            a, cW_r + cc, cW_k + cc, cW_v + cc, cW_g + cc, rkvg,
            nullptr, nullptr, M_, C_, C_, C_);
        wkv_kernel<<<B_*H_*2, 128>>>(rkvg, rkvg + M_*C_, rkvg + 2*M_*C_, wkv,
                                     bonus + hk, decay + hk);
        gn_silu_kernel<<<(M_*H_)/4, 128>>>(wkv, rkvg + 3*M_*C_, gated,
                                           gn_s + l*C_, gn_b + l*C_);
        tgemm<64,64,4,3,0><<<dim3(C_/64, M_/64, 1), 128, SMEM_SMALL>>>(
            gated, cW_o + cc, nullptr, nullptr, nullptr, x,
            x, nullptr, M_, C_, C_, C_);

        // ---- channel mixer ----
        ln_kernel<<<M_, 256>>>(x, nullptr, ln, cm_ln_s + l*C_, cm_ln_b + l*C_, 1e-5f, 0);
        lerp2_kernel<<<EW_BLOCKS, 256>>>(ln, cm_ts_in + l*C_, cm_ts_g + l*C_,
                                         a, a + M_*C_);
        tgemm<128,128,8,1,0><<<dim3(DFF_/128, M_/128, 1), 256, SMEM_BIG>>>(
            a, cW_in + fc, nullptr, nullptr, nullptr, hid,
            nullptr, nullptr, M_, DFF_, C_, C_);
        tgemm<64,64,4,2,0><<<dim3(C_/64, M_/64, 1), 128, SMEM_SMALL>>>(
            a + M_*C_, cW_gt + cc, nullptr, nullptr, nullptr, gate,
            nullptr, nullptr, M_, C_, C_, C_);
        // W_out: split-K = 4, partials into g_a (free now), then fused reduce
        tgemm<64,64,4,0,1><<<dim3(C_/64, M_/64, 4), 128, SMEM_SMALL>>>(
            hid, cW_out + oc, nullptr, nullptr, nullptr, a,
            nullptr, nullptr, M_, C_, DFF_/4, DFF_);
        reduce4_gate_kernel<<<EW_BLOCKS, 256>>>(a, gate, x, M_*C_);
    }

    ln_kernel<<<M_, 256>>>(x, nullptr, ln, head_ln_s, head_ln_b, 1e-5f, 1);
    tgemm<128,128,8,0,0><<<dim3(V_/128, M_/128, 1), 256, SMEM_BIG>>>(
        ln, cW_un, nullptr, nullptr, nullptr, (float*)d_out,
        nullptr, nullptr, M_, V_, C_, C_);
}

// round 7
// speedup vs baseline: 2.9701x; 1.7952x over previous
#include <cuda_runtime.h>
#include <cuda_fp16.h>
#include <math.h>
#include <mma.h>
#include <cstdint>

using namespace nvcuda;

// Problem dims
#define B_   2
#define T_   512
#define C_   768
#define H_   12
#define K_   64
#define L_   6
#define DFF_ 2688
#define V_   50304
#define M_   (B_*T_)   // 1024 rows

// weight family sizes (elements)
#define CCL  (L_*C_*C_)
#define FCL  (L_*DFF_*C_)
#define VCL  (V_*C_)

#define OFF_WR   0
#define OFF_WK   (OFF_WR + CCL)
#define OFF_WV   (OFF_WK + CCL)
#define OFF_WG   (OFF_WV + CCL)
#define OFF_WO   (OFF_WG + CCL)
#define OFF_WIN  (OFF_WO + CCL)
#define OFF_WOUT (OFF_WIN + FCL)
#define OFF_WGT  (OFF_WOUT + FCL)
#define OFF_WUN  (OFF_WGT + CCL)
#define WTF_TOT  (OFF_WUN + VCL)

// ---------------- scratch (device globals; no allocation allowed) ----------
__device__ __half g_wh  [WTF_TOT];    // fp16 weights
__device__ float  g_x   [M_*C_];
__device__ float  g_ln  [M_*C_];
__device__ __half g_ah  [4*M_*C_];    // half activations (lerp outs / head-ln)
__device__ __half g_hidh[M_*DFF_];    // half hidden (relu^2 out)
__device__ __half g_gath[M_*C_];      // half gated (gn*silu out)
__device__ float  g_part[4*M_*C_];    // split-K partials
__device__ float  g_rkvg[4*M_*C_];
__device__ float  g_wkv [M_*C_];
__device__ float  g_gate[M_*C_];

// ---------------- helpers ---------------------------------------------------
__device__ __forceinline__ void cp_async16(void* smem_dst, const void* gsrc) {
    unsigned dst = (unsigned)__cvta_generic_to_shared(smem_dst);
    asm volatile("cp.async.cg.shared.global [%0], [%1], 16;\n" :: "r"(dst), "l"(gsrc));
}
__device__ __forceinline__ void cp_commit() { asm volatile("cp.async.commit_group;\n"); }
__device__ __forceinline__ void cp_wait1()  { asm volatile("cp.async.wait_group 1;\n"); }
__device__ __forceinline__ void cp_wait0()  { asm volatile("cp.async.wait_group 0;\n"); }

// ---------------- fp32 -> fp16 weight conversion (once per call) -----------
__global__ void cvt_f2h_kernel(const float* __restrict__ src,
                               __half* __restrict__ dst, int n8)
{
    int i = blockIdx.x*blockDim.x + threadIdx.x;
    if (i >= n8) return;
    const float4* s4 = (const float4*)src;
    float4 a = s4[2*i], b = s4[2*i+1];
    __half2 h0 = __floats2half2_rn(a.x, a.y);
    __half2 h1 = __floats2half2_rn(a.z, a.w);
    __half2 h2 = __floats2half2_rn(b.x, b.y);
    __half2 h3 = __floats2half2_rn(b.z, b.w);
    uint4 o;
    o.x = *(uint32_t*)&h0; o.y = *(uint32_t*)&h1;
    o.z = *(uint32_t*)&h2; o.w = *(uint32_t*)&h3;
    ((uint4*)dst)[i] = o;
}

// ---------------- FP16 wmma GEMM, BK=32, cp.async double-buffered ----------
// C[M,N] = A[M,K(seg)] @ W[N,K(seg)]^T (+ epilogue). A,W are __half.
// EPI: 0 none | 1 relu()^2 -> half | 2 sigmoid | 3 +Res | 4 *Gate+Res
// SPLITK=0: grid.z selects weight among W0..W3. SPLITK=1: grid.z = K-segment.
// HOUT: write C as half (Ch) instead of float.
template<int BM, int BN, int WARPS, int EPI, int SPLITK, int HOUT>
__global__ void __launch_bounds__(WARPS*32, (WARPS==8)?2:4)
hgemm(const __half* __restrict__ Abase,
      const __half* __restrict__ W0, const __half* __restrict__ W1,
      const __half* __restrict__ W2, const __half* __restrict__ W3,
      float* __restrict__ Cbase, __half* __restrict__ Chbase,
      const float* __restrict__ Res, const float* __restrict__ Gate,
      int M, int N, int Kseg, int lda)
{
    constexpr int NT  = WARPS*32;
    constexpr int BK  = 32;
    constexpr int LDT = 40;                    // halves; 80B rows
    extern __shared__ __align__(16) __half sh[];
    __half* As = sh;                           // [2][BM*LDT]
    __half* Bs = sh + 2*BM*LDT;                // [2][BN*LDT]
    __shared__ __align__(16) float Ep[(EPI >= 3 || HOUT) ? WARPS*256 : 8];

    int z = blockIdx.z;
    const __half* A;
    const __half* W;
    float*  C  = nullptr;
    __half* Ch = nullptr;
    if (SPLITK) {
        A = Abase + (size_t)z*Kseg;
        W = W0    + (size_t)z*Kseg;
        C = Cbase + (size_t)z*M*N;
    } else {
        A = Abase + (size_t)z*M*lda;
        W = W0;
        if (z == 1) W = W1; else if (z == 2) W = W2; else if (z == 3) W = W3;
        if (HOUT) Ch = Chbase + (size_t)z*M*N;
        else      C  = Cbase  + (size_t)z*M*N;
    }

    int bm = blockIdx.y*BM, bn = blockIdx.x*BN;
    int tid = threadIdx.x, warp = tid>>5, lane = tid&31;
    constexpr int WC = (WARPS == 8) ? 4 : 2;
    int wm = warp / WC;
    int wn = warp % WC;
    constexpr int WM = BM/2;
    constexpr int WN = BN/WC;
    constexpr int MF = WM/16, NF = WN/16;

    wmma::fragment<wmma::accumulator,16,16,16,float> cf[MF][NF];
    #pragma unroll
    for (int i=0;i<MF;i++)
        #pragma unroll
        for (int j=0;j<NF;j++) wmma::fill_fragment(cf[i][j], 0.f);

    constexpr int A_CP = BM*(BK/8)/NT;   // cp16 ops per thread for A (=2)
    constexpr int B_CP = BN*(BK/8)/NT;

    const int nK = Kseg / BK;

    auto issue_stage = [&](int stg, int kt) {
        int k0 = kt*BK;
        __half* as = As + stg*BM*LDT;
        __half* bs = Bs + stg*BN*LDT;
        #pragma unroll
        for (int i=0;i<A_CP;i++){
            int idx = tid + i*NT;                 // over BM*4 chunks of 8 halves
            int row = idx >> 2, c8 = idx & 3;
            cp_async16(&as[row*LDT + c8*8],
                       A + (size_t)(bm+row)*lda + k0 + c8*8);
        }
        #pragma unroll
        for (int i=0;i<B_CP;i++){
            int idx = tid + i*NT;
            int row = idx >> 2, c8 = idx & 3;
            cp_async16(&bs[row*LDT + c8*8],
                       W + (size_t)(bn+row)*lda + k0 + c8*8);
        }
        cp_commit();
    };

    issue_stage(0, 0);

    for (int kt = 0; kt < nK; kt++) {
        if (kt + 1 < nK) { issue_stage((kt+1)&1, kt+1); cp_wait1(); }
        else             { cp_wait0(); }
        __syncthreads();
        int stg = kt & 1;
        const __half* as = As + stg*BM*LDT;
        const __half* bs = Bs + stg*BN*LDT;
        #pragma unroll
        for (int kk=0; kk<BK; kk+=16) {
            wmma::fragment<wmma::matrix_a,16,16,16,__half,wmma::row_major> af[MF];
            wmma::fragment<wmma::matrix_b,16,16,16,__half,wmma::col_major> bf[NF];
            #pragma unroll
            for (int i=0;i<MF;i++)
                wmma::load_matrix_sync(af[i], &as[(wm*WM + i*16)*LDT + kk], LDT);
            #pragma unroll
            for (int j=0;j<NF;j++)
                wmma::load_matrix_sync(bf[j], &bs[(wn*WN + j*16)*LDT + kk], LDT);
            #pragma unroll
            for (int i=0;i<MF;i++)
                #pragma unroll
                for (int j=0;j<NF;j++)
                    wmma::mma_sync(cf[i][j], af[i], bf[j], cf[i][j]);
        }
        __syncthreads();
    }

    // ---- epilogue ----
    #pragma unroll
    for (int i=0;i<MF;i++){
        #pragma unroll
        for (int j=0;j<NF;j++){
            int r0 = bm + wm*WM + i*16;
            int c0 = bn + wn*WN + j*16;
            if (!HOUT && EPI == 0) {
                wmma::store_matrix_sync(&C[(size_t)r0*N + c0], cf[i][j], N, wmma::mem_row_major);
            } else if (!HOUT && EPI == 2) {
                #pragma unroll
                for (int e=0;e<cf[i][j].num_elements;e++)
                    cf[i][j].x[e] = 1.f/(1.f + expf(-cf[i][j].x[e]));
                wmma::store_matrix_sync(&C[(size_t)r0*N + c0], cf[i][j], N, wmma::mem_row_major);
            } else {
                float* buf = &Ep[warp*256];
                wmma::store_matrix_sync(buf, cf[i][j], 16, wmma::mem_row_major);
                __syncwarp();
                #pragma unroll
                for (int e=0;e<8;e++){
                    int idx2 = lane*8 + e;
                    int rr = idx2>>4, cc2 = idx2&15;
                    size_t o = (size_t)(r0+rr)*N + (c0+cc2);
                    float v = buf[idx2];
                    if (EPI == 1) { v = fmaxf(v, 0.f); v = v*v; }
                    else if (EPI == 3) { v += Res[o]; }
                    else if (EPI == 4) { v = fmaf(v, Gate[o], Res[o]); }
                    if (HOUT) Ch[o] = __float2half_rn(v);
                    else      C[o]  = v;
                }
                __syncwarp();
            }
        }
    }
}

// ---------------- split-K reduce: x += (p0+p1+p2+p3) * gate ----------------
__global__ void reduce4_gate_kernel(const float* __restrict__ parts,
                                    const float* __restrict__ gate,
                                    float* __restrict__ x, int n)
{
    int idx = blockIdx.x*blockDim.x + threadIdx.x;
    if (idx >= n) return;
    float v = (parts[idx]               + parts[idx +   (size_t)n])
            + (parts[idx + 2*(size_t)n] + parts[idx + 3*(size_t)n]);
    x[idx] = fmaf(v, gate[idx], x[idx]);
}

// ---------------- LayerNorm over C=768 (one block / row, 256 threads) ------
// If hout != null, write half there; else write float to out.
__global__ void ln_kernel(const float* __restrict__ in,
                          const int*   __restrict__ tokens,
                          float*       __restrict__ out,
                          __half*      __restrict__ hout,
                          const float* __restrict__ s,
                          const float* __restrict__ bia,
                          float eps)
{
    int row = blockIdx.x;
    const float* xp = tokens ? (in + (size_t)tokens[row]*C_)
                             : (in + (size_t)row*C_);
    int tid = threadIdx.x;
    float v0 = xp[tid], v1 = xp[tid+256], v2 = xp[tid+512];

    __shared__ float red[8];
    __shared__ float s_mean, s_rstd;

    float sum = v0 + v1 + v2;
    #pragma unroll
    for (int o=16;o;o>>=1) sum += __shfl_xor_sync(0xffffffffu, sum, o);
    if ((tid & 31) == 0) red[tid>>5] = sum;
    __syncthreads();
    if (tid == 0) { float t=0.f; for (int i=0;i<8;i++) t += red[i]; s_mean = t*(1.f/C_); }
    __syncthreads();
    float m  = s_mean;
    float d0 = v0-m, d1 = v1-m, d2 = v2-m;
    float sq = d0*d0 + d1*d1 + d2*d2;
    #pragma unroll
    for (int o=16;o;o>>=1) sq += __shfl_xor_sync(0xffffffffu, sq, o);
    __syncthreads();
    if ((tid & 31) == 0) red[tid>>5] = sq;
    __syncthreads();
    if (tid == 0) { float t=0.f; for (int i=0;i<8;i++) t += red[i];
                    s_rstd = rsqrtf(t*(1.f/C_) + eps); }
    __syncthreads();
    float rs = s_rstd;
    float y0 = d0*rs*s[tid]     + bia[tid];
    float y1 = d1*rs*s[tid+256] + bia[tid+256];
    float y2 = d2*rs*s[tid+512] + bia[tid+512];
    if (hout) {
        __half* hp = hout + (size_t)row*C_;
        hp[tid]     = __float2half_rn(y0);
        hp[tid+256] = __float2half_rn(y1);
        hp[tid+512] = __float2half_rn(y2);
    } else {
        float* op = out + (size_t)row*C_;
        op[tid] = y0; op[tid+256] = y1; op[tid+512] = y2;
    }
}

// ---------------- token-shift + 4-way lerp -> half -------------------------
__global__ void lerp4_kernel(const float* __restrict__ ln,
                             const float* __restrict__ tr, const float* __restrict__ tk,
                             const float* __restrict__ tv, const float* __restrict__ tg,
                             __half* __restrict__ aout)
{
    int idx = blockIdx.x*blockDim.x + threadIdx.x;
    if (idx >= M_*C_) return;
    int c = idx % C_;
    int t = (idx / C_) % T_;
    float x  = ln[idx];
    float xs = (t == 0) ? 0.f : ln[idx - C_];
    float d  = xs - x;
    aout[idx]            = __float2half_rn(fmaf(tr[c], d, x));
    aout[idx +   M_*C_]  = __float2half_rn(fmaf(tk[c], d, x));
    aout[idx + 2*M_*C_]  = __float2half_rn(fmaf(tv[c], d, x));
    aout[idx + 3*M_*C_]  = __float2half_rn(fmaf(tg[c], d, x));
}

// ---------------- token-shift + 2-way lerp -> half -------------------------
__global__ void lerp2_kernel(const float* __restrict__ ln,
                             const float* __restrict__ ti, const float* __restrict__ tg,
                             __half* __restrict__ xi, __half* __restrict__ xg)
{
    int idx = blockIdx.x*blockDim.x + threadIdx.x;
    if (idx >= M_*C_) return;
    int c = idx % C_;
    int t = (idx / C_) % T_;
    float x  = ln[idx];
    float xs = (t == 0) ? 0.f : ln[idx - C_];
    float d  = xs - x;
    xi[idx] = __float2half_rn(fmaf(ti[c], d, x));
    xg[idx] = __float2half_rn(fmaf(tg[c], d, x));
}

// ---------------- WKV sequential scan (fp32, double-buffered) --------------
__global__ void wkv_kernel(const float* __restrict__ r, const float* __restrict__ k,
                           const float* __restrict__ v, float* __restrict__ out,
                           const float* __restrict__ bonus, const float* __restrict__ decay)
{
    int blk  = blockIdx.x;
    int vs   = blk & 1;
    int h    = (blk >> 1) % H_;
    int b    = blk / (2*H_);
    int tid  = threadIdx.x;
    int kc   = tid & 3;
    int vloc = tid >> 2;
    int vg   = vs*32 + vloc;

    size_t off = (size_t)b*T_*C_ + (size_t)h*K_;
    const float* rp = r + off;
    const float* kp = k + off;
    const float* vp = v + off;
    float*       op = out + off;

    float u[16], w[16], st[16];
    #pragma unroll
    for (int i = 0; i < 16; i++) {
        int kk = kc*16 + i;
        u[i]  = bonus[h*K_ + kk];
        w[i]  = expf(-expf(decay[h*K_ + kk]));
        st[i] = 0.f;
    }

    __shared__ float shr[2][64], shk[2][64];

    if (tid < 64) shr[0][tid]      = rp[tid];
    else          shk[0][tid - 64] = kp[tid - 64];
    float vv = vp[vg];
    __syncthreads();

    for (int t = 0; t < T_; t++) {
        int cur = t & 1, nxt = cur ^ 1;

        float nr = 0.f, nk = 0.f, nv = 0.f;
        if (t + 1 < T_) {
            size_t o1 = (size_t)(t+1)*C_;
            if (tid < 64) nr = rp[o1 + tid];
            else          nk = kp[o1 + tid - 64];
            nv = vp[o1 + vg];
        }

        float acc0 = 0.f, acc1 = 0.f;
        #pragma unroll
        for (int i = 0; i < 16; i += 2) {
            float k0 = shk[cur][kc*16 + i]     * vv;
            float k1 = shk[cur][kc*16 + i + 1] * vv;
            acc0  = fmaf(shr[cur][kc*16 + i],     fmaf(u[i],   k0, st[i]),   acc0);
            acc1  = fmaf(shr[cur][kc*16 + i + 1], fmaf(u[i+1], k1, st[i+1]), acc1);
            st[i]   = fmaf(st[i],   w[i],   k0);
            st[i+1] = fmaf(st[i+1], w[i+1], k1);
        }
        float acc = acc0 + acc1;
        acc += __shfl_xor_sync(0xffffffffu, acc, 1);
        acc += __shfl_xor_sync(0xffffffffu, acc, 2);
        if (kc == 0) op[(size_t)t*C_ + vg] = acc;

        if (t + 1 < T_) {
            if (tid < 64) shr[nxt][tid]      = nr;
            else          shk[nxt][tid - 64] = nk;
        }
        vv = nv;
        __syncthreads();
    }
}

// ---------------- GroupNorm(H groups of 64) * silu(g) -> half --------------
__global__ void gn_silu_kernel(const float* __restrict__ x, const float* __restrict__ g,
                               __half* __restrict__ out,
                               const float* __restrict__ s, const float* __restrict__ bb)
{
    int gid  = blockIdx.x*4 + (threadIdx.x >> 5);
    int lane = threadIdx.x & 31;
    int h    = gid % H_;
    int row  = gid / H_;

    const float* xp = x + (size_t)row*C_ + h*K_;
    float x0 = xp[lane], x1 = xp[lane+32];
    float sum = x0 + x1;
    #pragma unroll
    for (int o=16;o;o>>=1) sum += __shfl_xor_sync(0xffffffffu, sum, o);
    float m  = sum * (1.f/64.f);
    float d0 = x0-m, d1 = x1-m;
    float sq = d0*d0 + d1*d1;
    #pragma unroll
    for (int o=16;o;o>>=1) sq += __shfl_xor_sync(0xffffffffu, sq, o);
    float rstd = rsqrtf(sq*(1.f/64.f) + 0.00064f);

    int c0 = h*K_ + lane, c1 = c0 + 32;
    float y0 = fmaf(d0*rstd, s[c0], bb[c0]);
    float y1 = fmaf(d1*rstd, s[c1], bb[c1]);

    const float* gp = g + (size_t)row*C_ + h*K_;
    float g0 = gp[lane], g1 = gp[lane+32];
    y0 *= g0 / (1.f + expf(-g0));
    y1 *= g1 / (1.f + expf(-g1));

    __half* opp = out + (size_t)row*C_ + h*K_;
    opp[lane]    = __float2half_rn(y0);
    opp[lane+32] = __float2half_rn(y1);
}

// ---------------- orchestration --------------------------------------------
#define SMEM_BIG   (2*(128+128)*40*2)    // 40960 B
#define SMEM_SMALL (2*(64+64)*40*2)      // 20480 B

extern "C" void kernel_launch(void* const* d_in, const int* in_sizes, int n_in,
                              void* d_out, int out_size)
{
    (void)in_sizes; (void)n_in; (void)out_size;
    const int*   tokens    = (const int*)  d_in[0];
    const float* embed     = (const float*)d_in[1];
    const float* emb_ln_s  = (const float*)d_in[2];
    const float* emb_ln_b  = (const float*)d_in[3];
    const float* tm_ln_s   = (const float*)d_in[4];
    const float* tm_ln_b   = (const float*)d_in[5];
    const float* ts_r      = (const float*)d_in[6];
    const float* ts_k      = (const float*)d_in[7];
    const float* ts_v      = (const float*)d_in[8];
    const float* ts_g      = (const float*)d_in[9];
    const float* W_r       = (const float*)d_in[10];
    const float* W_k       = (const float*)d_in[11];
    const float* W_v       = (const float*)d_in[12];
    const float* W_g       = (const float*)d_in[13];
    const float* W_o       = (const float*)d_in[14];
    const float* bonus     = (const float*)d_in[15];
    const float* decay     = (const float*)d_in[16];
    const float* gn_s      = (const float*)d_in[17];
    const float* gn_b      = (const float*)d_in[18];
    const float* cm_ln_s   = (const float*)d_in[19];
    const float* cm_ln_b   = (const float*)d_in[20];
    const float* cm_ts_in  = (const float*)d_in[21];
    const float* cm_ts_g   = (const float*)d_in[22];
    const float* W_in      = (const float*)d_in[23];
    const float* W_out     = (const float*)d_in[24];
    const float* W_gate    = (const float*)d_in[25];
    const float* head_ln_s = (const float*)d_in[26];
    const float* head_ln_b = (const float*)d_in[27];
    const float* W_unembed = (const float*)d_in[28];

    __half *wh, *ah, *hidh, *gath;
    float *x, *ln, *part, *rkvg, *wkv, *gate;
    cudaGetSymbolAddress((void**)&wh,   g_wh);
    cudaGetSymbolAddress((void**)&x,    g_x);
    cudaGetSymbolAddress((void**)&ln,   g_ln);
    cudaGetSymbolAddress((void**)&ah,   g_ah);
    cudaGetSymbolAddress((void**)&hidh, g_hidh);
    cudaGetSymbolAddress((void**)&gath, g_gath);
    cudaGetSymbolAddress((void**)&part, g_part);
    cudaGetSymbolAddress((void**)&rkvg, g_rkvg);
    cudaGetSymbolAddress((void**)&wkv,  g_wkv);
    cudaGetSymbolAddress((void**)&gate, g_gate);

    // opt-in dynamic smem (idempotent)
    cudaFuncSetAttribute(hgemm<128,128,8,0,0,0>, cudaFuncAttributeMaxDynamicSharedMemorySize, SMEM_BIG);
    cudaFuncSetAttribute(hgemm<128,128,8,1,0,1>, cudaFuncAttributeMaxDynamicSharedMemorySize, SMEM_BIG);
    cudaFuncSetAttribute(hgemm<64,64,4,2,0,0>,   cudaFuncAttributeMaxDynamicSharedMemorySize, SMEM_SMALL);
    cudaFuncSetAttribute(hgemm<64,64,4,3,0,0>,   cudaFuncAttributeMaxDynamicSharedMemorySize, SMEM_SMALL);
    cudaFuncSetAttribute(hgemm<64,64,4,0,1,0>,   cudaFuncAttributeMaxDynamicSharedMemorySize, SMEM_SMALL);

    // ---- one-pass fp16 conversion of all weights ----
    auto cvt = [&](const float* src, __half* dst, long n) {
        int n8 = (int)(n/8);
        cvt_f2h_kernel<<<(n8 + 255)/256, 256>>>(src, dst, n8);
    };
    cvt(W_r,       wh + OFF_WR,   CCL);
    cvt(W_k,       wh + OFF_WK,   CCL);
    cvt(W_v,       wh + OFF_WV,   CCL);
    cvt(W_g,       wh + OFF_WG,   CCL);
    cvt(W_o,       wh + OFF_WO,   CCL);
    cvt(W_in,      wh + OFF_WIN,  FCL);
    cvt(W_out,     wh + OFF_WOUT, FCL);
    cvt(W_gate,    wh + OFF_WGT,  CCL);
    cvt(W_unembed, wh + OFF_WUN,  VCL);

    const __half* cW_r  = wh + OFF_WR;
    const __half* cW_k  = wh + OFF_WK;
    const __half* cW_v  = wh + OFF_WV;
    const __half* cW_g  = wh + OFF_WG;
    const __half* cW_o  = wh + OFF_WO;
    const __half* cW_in = wh + OFF_WIN;
    const __half* cW_out= wh + OFF_WOUT;
    const __half* cW_gt = wh + OFF_WGT;
    const __half* cW_un = wh + OFF_WUN;

    const int EW_BLOCKS = (M_*C_ + 255)/256;

    ln_kernel<<<M_, 256>>>(embed, tokens, x, nullptr, emb_ln_s, emb_ln_b, 1e-5f);

    for (int l = 0; l < L_; l++) {
        size_t cc = (size_t)l*C_*C_;
        size_t fc = (size_t)l*DFF_*C_;
        size_t oc = (size_t)l*C_*DFF_;
        size_t hk = (size_t)l*H_*K_;

        // ---- time mixer ----
        ln_kernel<<<M_, 256>>>(x, nullptr, ln, nullptr, tm_ln_s + l*C_, tm_ln_b + l*C_, 1e-5f);
        lerp4_kernel<<<EW_BLOCKS, 256>>>(ln, ts_r + l*C_, ts_k + l*C_,
                                         ts_v + l*C_, ts_g + l*C_, ah);
        hgemm<128,128,8,0,0,0><<<dim3(C_/128, M_/128, 4), 256, SMEM_BIG>>>(
            ah, cW_r + cc, cW_k + cc, cW_v + cc, cW_g + cc, rkvg, nullptr,
            nullptr, nullptr, M_, C_, C_, C_);
        wkv_kernel<<<B_*H_*2, 128>>>(rkvg, rkvg + M_*C_, rkvg + 2*M_*C_, wkv,
                                     bonus + hk, decay + hk);
        gn_silu_kernel<<<(M_*H_)/4, 128>>>(wkv, rkvg + 3*M_*C_, gath,
                                           gn_s + l*C_, gn_b + l*C_);
        hgemm<64,64,4,3,0,0><<<dim3(C_/64, M_/64, 1), 128, SMEM_SMALL>>>(
            gath, cW_o + cc, nullptr, nullptr, nullptr, x, nullptr,
            x, nullptr, M_, C_, C_, C_);

        // ---- channel mixer ----
        ln_kernel<<<M_, 256>>>(x, nullptr, ln, nullptr, cm_ln_s + l*C_, cm_ln_b + l*C_, 1e-5f);
        lerp2_kernel<<<EW_BLOCKS, 256>>>(ln, cm_ts_in + l*C_, cm_ts_g + l*C_,
                                         ah, ah + M_*C_);
        hgemm<128,128,8,1,0,1><<<dim3(DFF_/128, M_/128, 1), 256, SMEM_BIG>>>(
            ah, cW_in + fc, nullptr, nullptr, nullptr, nullptr, hidh,
            nullptr, nullptr, M_, DFF_, C_, C_);
        hgemm<64,64,4,2,0,0><<<dim3(C_/64, M_/64, 1), 128, SMEM_SMALL>>>(
            ah + M_*C_, cW_gt + cc, nullptr, nullptr, nullptr, gate, nullptr,
            nullptr, nullptr, M_, C_, C_, C_);
        // W_out: split-K = 4, partials, fused reduce*gate + residual
        hgemm<64,64,4,0,1,0><<<dim3(C_/64, M_/64, 4), 128, SMEM_SMALL>>>(
            hidh, cW_out + oc, nullptr, nullptr, nullptr, part, nullptr,
            nullptr, nullptr, M_, C_, DFF_/4, DFF_);
        reduce4_gate_kernel<<<EW_BLOCKS, 256>>>(part, gate, x, M_*C_);
    }

    // head LN -> half, unembed
    ln_kernel<<<M_, 256>>>(x, nullptr, nullptr, ah, head_ln_s, head_ln_b, 1e-5f);
    hgemm<128,128,8,0,0,0><<<dim3(V_/128, M_/128, 1), 256, SMEM_BIG>>>(
        ah, cW_un, nullptr, nullptr, nullptr, (float*)d_out, nullptr,
        nullptr, nullptr, M_, V_, C_, C_);
}